// round 8
// baseline (speedup 1.0000x reference)
#include <cuda_runtime.h>
#include <cuda_fp16.h>
#include <cstdint>
#include <cstddef>

#define DIMN   1024
#define HEADS  16
#define HDIM   64
#define BATCH  4
#define SEQ    1024
#define BHN    (BATCH*HEADS)
#define NB     33

#define GM (BATCH*SEQ)
#define GN DIMN
#define GK DIMN

typedef __half h16;

// ---------------- scratch (device globals; no allocation allowed) ----------
__device__ h16 g_xhi[GM*GK];
__device__ h16 g_xlo[GM*GK];
__device__ h16 g_whi[GN*GK];
__device__ h16 g_qhh[BHN*SEQ*HDIM];
__device__ h16 g_qhl[BHN*SEQ*HDIM];
__device__ h16 g_khh[BHN*SEQ*HDIM];
__device__ h16 g_vhh[BHN*SEQ*HDIM];
__device__ h16 g_vth[BHN*HDIM*SEQ];

// ---------------- helpers ---------------------------------------------------
__device__ __forceinline__ void mma16h(float* d, const uint32_t* a, const uint32_t* b) {
    asm volatile(
        "mma.sync.aligned.m16n8k16.row.col.f32.f16.f16.f32 "
        "{%0,%1,%2,%3},{%4,%5,%6,%7},{%8,%9},{%0,%1,%2,%3};"
        : "+f"(d[0]), "+f"(d[1]), "+f"(d[2]), "+f"(d[3])
        : "r"(a[0]), "r"(a[1]), "r"(a[2]), "r"(a[3]), "r"(b[0]), "r"(b[1]));
}
__device__ __forceinline__ void ldsm4(uint32_t* r, uint32_t addr) {
    asm volatile("ldmatrix.sync.aligned.m8n8.x4.shared.b16 {%0,%1,%2,%3}, [%4];"
        : "=r"(r[0]), "=r"(r[1]), "=r"(r[2]), "=r"(r[3]) : "r"(addr));
}
__device__ __forceinline__ void ldsm2(uint32_t* r, uint32_t addr) {
    asm volatile("ldmatrix.sync.aligned.m8n8.x2.shared.b16 {%0,%1}, [%2];"
        : "=r"(r[0]), "=r"(r[1]) : "r"(addr));
}
__device__ __forceinline__ uint32_t smem_u32(const void* p) {
    uint32_t r;
    asm("{ .reg .u64 t; cvta.to.shared.u64 t, %1; cvt.u32.u64 %0, t; }" : "=r"(r) : "l"(p));
    return r;
}
__device__ __forceinline__ uint32_t pack2h(float x, float y) {
    uint32_t r;
    h16 a = __float2half_rn(x), b = __float2half_rn(y);
    asm("mov.b32 %0, {%1, %2};" : "=r"(r) : "h"(*(uint16_t*)&a), "h"(*(uint16_t*)&b));
    return r;
}
#define CP16(dst_u32, src_ptr) \
    asm volatile("cp.async.cg.shared.global [%0], [%1], 16;" :: "r"(dst_u32), "l"(src_ptr))
#define CP_COMMIT() asm volatile("cp.async.commit_group;")
#define CP_WAIT1()  asm volatile("cp.async.wait_group 1;")
#define CP_WAIT0()  asm volatile("cp.async.wait_group 0;")

// ---------------- split fp32 -> fp16 hi/lo ----------------------------------
__global__ __launch_bounds__(256)
void split_x_kernel(const float* __restrict__ src,
                    h16* __restrict__ hi, h16* __restrict__ lo, int n4)
{
    int i = blockIdx.x * 256 + threadIdx.x;
    if (i >= n4) return;
    float4 v = ((const float4*)src)[i];
    float f[4] = {v.x, v.y, v.z, v.w};
    h16 h[4], l[4];
    #pragma unroll
    for (int j = 0; j < 4; j++) {
        h[j] = __float2half_rn(f[j]);
        l[j] = __float2half_rn(f[j] - __half2float(h[j]));
    }
    *(uint2*)&hi[(size_t)i*4] = *(uint2*)h;
    *(uint2*)&lo[(size_t)i*4] = *(uint2*)l;
}
__global__ __launch_bounds__(256)
void conv_w_kernel(const float* __restrict__ src, h16* __restrict__ hi, int n4)
{
    int i = blockIdx.x * 256 + threadIdx.x;
    if (i >= n4) return;
    float4 v = ((const float4*)src)[i];
    h16 h[4] = { __float2half_rn(v.x), __float2half_rn(v.y),
                 __float2half_rn(v.z), __float2half_rn(v.w) };
    *(uint2*)&hi[(size_t)i*4] = *(uint2*)h;
}

// ---------------- V transpose: [bh][t][d] -> [bh][d][t] (hi only) -----------
__global__ __launch_bounds__(256)
void vtrans_kernel(const h16* __restrict__ ih, h16* __restrict__ oh)
{
    __shared__ h16 th[64*136];
    const int bh = blockIdx.y, t0 = blockIdx.x * 128, tid = threadIdx.x;
    #pragma unroll
    for (int it = 0; it < 4; it++) {
        int idx = tid + it*256;
        int r = idx >> 3, c8 = idx & 7;
        h16 a[8];
        *(uint4*)a = *(const uint4*)&ih[((size_t)bh*1024 + t0 + r)*64 + c8*8];
        #pragma unroll
        for (int j = 0; j < 8; j++) th[(c8*8 + j)*136 + r] = a[j];
    }
    __syncthreads();
    #pragma unroll
    for (int it = 0; it < 4; it++) {
        int idx = tid + it*256;
        int d = idx >> 4, tc = idx & 15;
        h16 a[8];
        #pragma unroll
        for (int j = 0; j < 8; j++) a[j] = th[d*136 + tc*8 + j];
        *(uint4*)&oh[((size_t)bh*64 + d)*1024 + t0 + tc*8] = *(uint4*)a;
    }
}

// ---------------- fp16x2 GEMM: C = X @ W^T + bias, *scale -------------------
// M=4096,N=1024,K=1024. 128x128 tile, BK=32, cp.async double-buffered, LDSM.
// mode 0: fp32 out. mode 1: head layout hi+lo. mode 2: head layout hi only.
#define TILEB  (128*80)            // one 128x32-halves tile, 80B rows
#define STAGEB (3*TILEB)           // Ah, Al, Bh
#define GEMM_SMEM_BYTES (2*STAGEB) // 61440

__global__ __launch_bounds__(256, 2)
void gemm_fp16_kernel(const h16* __restrict__ Xh, const h16* __restrict__ Xl,
                      const h16* __restrict__ Wh,
                      const float* __restrict__ bias, float* __restrict__ outf,
                      h16* __restrict__ oh, h16* __restrict__ ol,
                      float scale, int mode)
{
    extern __shared__ char gsm[];
    const uint32_t sb = smem_u32(gsm);
    const int tid  = threadIdx.x;
    const int m0   = blockIdx.y * 128;
    const int n0   = blockIdx.x * 128;
    const int warp = tid >> 5, lane = tid & 31;
    const int gid  = lane >> 2, tig = lane & 3;
    const int wm   = warp >> 2, wn = warp & 3;

    const uint32_t aoffB = (uint32_t)((lane & 15)*80 + ((lane >> 4) << 4));
    const uint32_t boffB = (uint32_t)(((lane & 7) + ((lane >> 4) << 3))*80 + (((lane >> 3) & 1) << 4));

    const h16* srcs[3] = { Xh, Xl, Wh };

    float acc[4][4][4];
    #pragma unroll
    for (int i = 0; i < 4; i++)
        #pragma unroll
        for (int j = 0; j < 4; j++)
            #pragma unroll
            for (int e = 0; e < 4; e++) acc[i][j][e] = 0.f;

    auto fill = [&](int s) {
        const int k0 = s * 32;
        const uint32_t bU = sb + (uint32_t)(s & 1) * STAGEB;
        #pragma unroll
        for (int t = 0; t < 3; t++) {
            const h16* src = srcs[t];
            const int r0 = (t < 2) ? m0 : n0;
            #pragma unroll
            for (int it = 0; it < 2; it++) {
                int idx = tid + it * 256;
                int r = idx >> 2, c = idx & 3;
                CP16(bU + t*TILEB + (uint32_t)(r*80 + c*16),
                     src + (size_t)(r0 + r) * GK + k0 + c*8);
            }
        }
        CP_COMMIT();
    };

    fill(0);
    fill(1);
    for (int t = 0; t < 32; t++) {
        if (t < 31) CP_WAIT1(); else CP_WAIT0();
        __syncthreads();

        const uint32_t st  = sb + (uint32_t)(t & 1) * STAGEB;
        const uint32_t AhU = st;
        const uint32_t AlU = st + TILEB;
        const uint32_t BhU = st + 2*TILEB;

        #pragma unroll
        for (int kkb = 0; kkb < 64; kkb += 32) {   // byte offset of k16 step
            uint32_t bf[2][4];
            ldsm4(bf[0], BhU + (uint32_t)((wn*32     )*80) + boffB + kkb);
            ldsm4(bf[1], BhU + (uint32_t)((wn*32 + 16)*80) + boffB + kkb);
            #pragma unroll
            for (int i = 0; i < 4; i++) {
                uint32_t ah[4], al[4];
                uint32_t rb = (uint32_t)((wm*64 + i*16)*80) + aoffB + kkb;
                ldsm4(ah, AhU + rb);
                ldsm4(al, AlU + rb);
                #pragma unroll
                for (int j = 0; j < 4; j++) {
                    const uint32_t* b = &bf[j >> 1][(j & 1)*2];
                    mma16h(acc[i][j], ah, b);
                    mma16h(acc[i][j], al, b);
                }
            }
        }
        __syncthreads();
        if (t + 2 < 32) fill(t + 2);
    }

    // epilogue
    #pragma unroll
    for (int i = 0; i < 4; i++) {
        int r0 = m0 + wm*64 + i*16 + gid;
        #pragma unroll
        for (int j = 0; j < 4; j++) {
            int nc = n0 + wn*32 + j*8 + 2*tig;
            float b0 = bias[nc], b1 = bias[nc + 1];
            float v00 = (acc[i][j][0] + b0) * scale;
            float v01 = (acc[i][j][1] + b1) * scale;
            float v10 = (acc[i][j][2] + b0) * scale;
            float v11 = (acc[i][j][3] + b1) * scale;
            if (mode == 0) {
                *(float2*)(outf + (size_t)r0 * GN + nc)       = make_float2(v00, v01);
                *(float2*)(outf + (size_t)(r0 + 8) * GN + nc) = make_float2(v10, v11);
            } else {
                int h = nc >> 6, d = nc & 63;
                int b0i = r0 >> 10, t0 = r0 & (SEQ - 1);
                int b1i = (r0 + 8) >> 10, t1 = (r0 + 8) & (SEQ - 1);
                size_t a0 = ((size_t)((b0i*HEADS + h)*SEQ + t0))*HDIM + d;
                size_t a1 = ((size_t)((b1i*HEADS + h)*SEQ + t1))*HDIM + d;
                *(uint32_t*)&oh[a0] = pack2h(v00, v01);
                *(uint32_t*)&oh[a1] = pack2h(v10, v11);
                if (mode == 1) {
                    h16 h00 = __float2half_rn(v00), h01 = __float2half_rn(v01);
                    h16 h10 = __float2half_rn(v10), h11 = __float2half_rn(v11);
                    *(uint32_t*)&ol[a0] = pack2h(v00 - __half2float(h00), v01 - __half2float(h01));
                    *(uint32_t*)&ol[a1] = pack2h(v10 - __half2float(h10), v11 - __half2float(h11));
                }
            }
        }
    }
}

// ---------------- attention kernel ------------------------------------------
#define TQ   32
#define ESTR 1036
// byte offsets in dynamic smem
#define B_E     0
#define B_QH    (TQ*ESTR*4)            // 132608
#define B_QL    (B_QH + TQ*144)        // 137216
#define B_KV    (B_QL + TQ*144)        // 141824  (two 18432B tile buffers)
#define B_RWV   (B_KV + 2*18432)       // 178688
#define B_PROJ  (B_RWV + NB*64*4)      // 187136
#define B_SROW  (B_PROJ + TQ*NB*4)     // 191360
#define B_RPECV (B_SROW + TQ*NB*4)     // 195584
#define ATT_SMEM_BYTES (B_RPECV + TQ*64*4)  // 203776

__device__ __forceinline__ int rpe_clip(int dd) {
    dd = dd < -16 ? -16 : (dd > 16 ? 16 : dd);
    return dd + 16;
}

__global__ __launch_bounds__(512)
void attn_kernel(const float* __restrict__ rpe_w, float* __restrict__ align_out)
{
    extern __shared__ char smc[];
    float* e     = (float*)smc;
    float* rwv   = (float*)(smc + B_RWV);
    float* proj  = (float*)(smc + B_PROJ);
    float* srow  = (float*)(smc + B_SROW);
    float* rpecv = (float*)(smc + B_RPECV);

    const uint32_t sbase = smem_u32(smc);
    const uint32_t sE = sbase, sQH = sbase + B_QH, sQL = sbase + B_QL, sKV = sbase + B_KV;

    const int bhid = blockIdx.y;
    const int q0   = blockIdx.x * TQ;
    const int tid  = threadIdx.x;
    const int warp = tid >> 5, lane = tid & 31;
    const int gid  = lane >> 2, tig = lane & 3;

    // ---- prologue: Q hi/lo tiles, rpe_v table ----
    {
        int r = (tid & 255) >> 3, c = tid & 7;
        const h16* src = (tid < 256) ? g_qhh : g_qhl;
        char* dst = smc + ((tid < 256) ? B_QH : B_QL);
        *(uint4*)(dst + r*144 + c*16) =
            *(const uint4*)&src[((size_t)bhid*SEQ + q0 + r)*HDIM + c*8];
    }
    for (int i = tid; i < NB*64; i += 512) {
        int t = i >> 6, d = i & 63;
        rwv[i] = rpe_w[t*128 + 64 + d];
    }
    __syncthreads();

    // proj[q][t] = qh[q] . rpe_w[t, 0:64]
    {
        const h16* qh16 = (const h16*)(smc + B_QH);
        const h16* ql16 = (const h16*)(smc + B_QL);
        for (int i = tid; i < TQ*NB; i += 512) {
            int q = i / NB, t = i - q*NB;
            const float* rp = rpe_w + t*128;
            float s = 0.f;
            #pragma unroll 16
            for (int d = 0; d < 64; d++)
                s += (__half2float(qh16[q*72 + d]) + __half2float(ql16[q*72 + d])) * __ldg(&rp[d]);
            proj[i] = s;
        }
    }

    // ---- hoist Q fragments (constant across kt) ----
    const int mS = warp & 1;
    const int np = warp >> 1;
    const uint32_t aoffQ = (uint32_t)((lane & 15)*144 + ((lane >> 4) << 4));
    const uint32_t boffS = (uint32_t)(((lane & 7) + ((lane >> 4) << 3))*144 + (((lane >> 3) & 1) << 4));
    uint32_t qhf[4][4], qlf[4][4];
    {
        uint32_t qb = (uint32_t)(mS*16*144) + aoffQ;
        #pragma unroll
        for (int ks = 0; ks < 4; ks++) {
            ldsm4(qhf[ks], sQH + qb + ks*32);
            ldsm4(qlf[ks], sQL + qb + ks*32);
        }
    }

    // ---- S = Q K^T (fp16x2, LDSM) + rpe_q ----
    auto fillK = [&](int ktI) {
        uint32_t bU = sKV + (uint32_t)(ktI & 1)*18432;
        const h16* kb = g_khh + ((size_t)bhid*SEQ + ktI*128)*HDIM;
        #pragma unroll
        for (int it = 0; it < 2; it++) {
            int idx = tid + it*512;
            int r = idx >> 3, c = idx & 7;
            CP16(bU + (uint32_t)(r*144 + c*16), kb + (size_t)r*64 + c*8);
        }
        CP_COMMIT();
    };

    fillK(0);
    for (int ktI = 0; ktI < 8; ktI++) {
        if (ktI < 7) { fillK(ktI + 1); CP_WAIT1(); } else CP_WAIT0();
        __syncthreads();

        uint32_t KU = sKV + (uint32_t)(ktI & 1)*18432 + (uint32_t)(np*16*144);
        float acc[2][4] = {{0.f,0.f,0.f,0.f},{0.f,0.f,0.f,0.f}};
        #pragma unroll
        for (int ks = 0; ks < 4; ks++) {
            uint32_t bf[4];
            ldsm4(bf, KU + boffS + ks*32);
            mma16h(acc[0], qhf[ks], bf);
            mma16h(acc[0], qlf[ks], bf);
            mma16h(acc[1], qhf[ks], bf + 2);
            mma16h(acc[1], qlf[ks], bf + 2);
        }
        int qA = mS*16 + gid, qB = qA + 8;
        int qgA = q0 + qA, qgB = q0 + qB;
        int kt = ktI * 128;
        #pragma unroll
        for (int jj = 0; jj < 2; jj++) {
            int k0c = kt + np*16 + jj*8 + 2*tig;
            e[qA*ESTR + k0c    ] = acc[jj][0] + proj[qA*NB + rpe_clip(qgA - k0c)];
            e[qA*ESTR + k0c + 1] = acc[jj][1] + proj[qA*NB + rpe_clip(qgA - k0c - 1)];
            e[qB*ESTR + k0c    ] = acc[jj][2] + proj[qB*NB + rpe_clip(qgB - k0c)];
            e[qB*ESTR + k0c + 1] = acc[jj][3] + proj[qB*NB + rpe_clip(qgB - k0c - 1)];
        }
        __syncthreads();
    }

    // prefetch V tiles 0,1 (overlaps with softmax)
    auto fillV = [&](int ktI) {
        uint32_t bU = sKV + (uint32_t)(ktI & 1)*18432;
        const h16* vb = g_vth + (size_t)bhid*HDIM*SEQ + ktI*128;
        #pragma unroll
        for (int it = 0; it < 2; it++) {
            int idx = tid + it*512;
            int r = idx >> 4, c = idx & 15;
            CP16(bU + (uint32_t)(r*272 + c*16), vb + (size_t)r*SEQ + c*8);
        }
        CP_COMMIT();
    };
    fillV(0);
    fillV(1);

    // ---- softmax + alignment + buckets + P fp16 pack (vectorized) ----
    for (int q = warp*2; q < warp*2 + 2; q++) {
        int qglob = q0 + q;
        float* row = e + q*ESTR;
        float ev[32];
        float mx = -1e30f;
        #pragma unroll
        for (int i = 0; i < 8; i++) {
            float4 vv = *(float4*)&row[i*128 + lane*4];
            ev[i*4+0] = vv.x; ev[i*4+1] = vv.y; ev[i*4+2] = vv.z; ev[i*4+3] = vv.w;
            mx = fmaxf(mx, fmaxf(fmaxf(vv.x, vv.y), fmaxf(vv.z, vv.w)));
        }
        #pragma unroll
        for (int o = 16; o; o >>= 1) mx = fmaxf(mx, __shfl_xor_sync(0xffffffffu, mx, o));
        float sum = 0.f;
        #pragma unroll
        for (int i = 0; i < 32; i++) { ev[i] = __expf(ev[i] - mx); sum += ev[i]; }
        #pragma unroll
        for (int o = 16; o; o >>= 1) sum += __shfl_xor_sync(0xffffffffu, sum, o);
        float inv = 1.f / sum;

        if (lane) srow[q*NB + lane] = 0.f;
        __syncwarp();

        float slo = 0.f, shi = 0.f;
        h16* hid = (h16*)row;
        h16* lod = hid + 1024;
        float* arow = align_out + ((size_t)(bhid * SEQ + qglob)) * SEQ;
        #pragma unroll
        for (int i = 0; i < 8; i++) {
            int k0 = i*128 + lane*4;
            float p[4];
            #pragma unroll
            for (int c = 0; c < 4; c++) p[c] = ev[i*4 + c] * inv;
            *(float4*)&arow[k0] = make_float4(p[0], p[1], p[2], p[3]);
            h16 ph[4];
            #pragma unroll
            for (int c = 0; c < 4; c++) ph[c] = __float2half_rn(p[c]);
            *(uint2*)&hid[k0] = *(uint2*)ph;
            h16 pl[4];
            #pragma unroll
            for (int c = 0; c < 4; c++) pl[c] = __float2half_rn(p[c] - __half2float(ph[c]));
            *(uint2*)&lod[k0] = *(uint2*)pl;
            #pragma unroll
            for (int c = 0; c < 4; c++) {
                int dd = qglob - (k0 + c);
                if (dd >= 16)       slo += p[c];
                else if (dd <= -16) shi += p[c];
                else                srow[q*NB + dd + 16] = p[c];
            }
        }
        #pragma unroll
        for (int o = 16; o; o >>= 1) {
            slo += __shfl_xor_sync(0xffffffffu, slo, o);
            shi += __shfl_xor_sync(0xffffffffu, shi, o);
        }
        if (lane == 0) { srow[q*NB + 32] = slo; srow[q*NB + 0] = shi; }
    }
    __syncthreads();

    // ---- rpecv[32][64] = srow @ rpe_v ----
    for (int i = tid; i < TQ*64; i += 512) {
        int q = i >> 6, d = i & 63;
        float s = 0.f;
        #pragma unroll
        for (int t = 0; t < NB; t++) s += srow[q*NB + t] * rwv[t*64 + d];
        rpecv[i] = s;
    }

    // ---- PV (fp16x2, LDSM) ----
    const int mP = warp & 1;
    const int nt = warp >> 1;
    const uint32_t aoffP = (uint32_t)((lane & 15)*(ESTR*4) + ((lane >> 4) << 4));
    const uint32_t boffV = (uint32_t)((nt*8 + (lane & 7))*272 + (((lane >> 3) & 1) << 4));
    float accP[4] = {0.f, 0.f, 0.f, 0.f};
    for (int ktI = 0; ktI < 8; ktI++) {
        if (ktI < 7) CP_WAIT1(); else CP_WAIT0();
        __syncthreads();
        uint32_t VU = sKV + (uint32_t)(ktI & 1)*18432;
        uint32_t PB = sE + (uint32_t)(mP*16*(ESTR*4)) + aoffP + (uint32_t)(ktI*256);
        #pragma unroll
        for (int ks = 0; ks < 8; ks++) {
            uint32_t ph[4], pl[4], bv[2];
            ldsm4(ph, PB + ks*32);
            ldsm4(pl, PB + 2048 + ks*32);
            ldsm2(bv, VU + boffV + ks*32);
            mma16h(accP, ph, bv);
            mma16h(accP, pl, bv);
        }
        __syncthreads();
        if (ktI + 2 < 8) fillV(ktI + 2);
    }

    // ---- epilogue: + rpecv, write ctx fp16 hi/lo into g_xhi/g_xlo ----
    {
        int qA = mP*16 + gid, qB = qA + 8;
        int d0 = nt*8 + 2*tig;
        int b = bhid >> 4, h = bhid & 15;
        float v00 = accP[0] + rpecv[qA*64 + d0];
        float v01 = accP[1] + rpecv[qA*64 + d0 + 1];
        float v10 = accP[2] + rpecv[qB*64 + d0];
        float v11 = accP[3] + rpecv[qB*64 + d0 + 1];
        size_t a0 = (size_t)(b*SEQ + q0 + qA)*DIMN + h*HDIM + d0;
        size_t a1 = (size_t)(b*SEQ + q0 + qB)*DIMN + h*HDIM + d0;
        h16 h00 = __float2half_rn(v00), h01 = __float2half_rn(v01);
        h16 h10 = __float2half_rn(v10), h11 = __float2half_rn(v11);
        *(uint32_t*)&g_xhi[a0] = pack2h(v00, v01);
        *(uint32_t*)&g_xhi[a1] = pack2h(v10, v11);
        *(uint32_t*)&g_xlo[a0] = pack2h(v00 - __half2float(h00), v01 - __half2float(h01));
        *(uint32_t*)&g_xlo[a1] = pack2h(v10 - __half2float(h10), v11 - __half2float(h11));
    }
}

// ---------------- launch ---------------------------------------------------
extern "C" void kernel_launch(void* const* d_in, const int* in_sizes, int n_in,
                              void* d_out, int out_size)
{
    const float* q     = (const float*)d_in[0];
    const float* k     = (const float*)d_in[1];
    const float* v     = (const float*)d_in[2];
    const float* Wq    = (const float*)d_in[3];
    const float* bq    = (const float*)d_in[4];
    const float* Wk    = (const float*)d_in[5];
    const float* bk    = (const float*)d_in[6];
    const float* Wv    = (const float*)d_in[7];
    const float* bv    = (const float*)d_in[8];
    const float* rpe_w = (const float*)d_in[9];
    const float* Wo    = (const float*)d_in[10];
    const float* bo    = (const float*)d_in[11];
    float* outp = (float*)d_out;

    h16 *xhi, *xlo, *whi, *qhh, *qhl, *khh, *vhh, *vth;
    cudaGetSymbolAddress((void**)&xhi, g_xhi);
    cudaGetSymbolAddress((void**)&xlo, g_xlo);
    cudaGetSymbolAddress((void**)&whi, g_whi);
    cudaGetSymbolAddress((void**)&qhh, g_qhh);
    cudaGetSymbolAddress((void**)&qhl, g_qhl);
    cudaGetSymbolAddress((void**)&khh, g_khh);
    cudaGetSymbolAddress((void**)&vhh, g_vhh);
    cudaGetSymbolAddress((void**)&vth, g_vth);

    static int inited = 0;
    if (!inited) {
        cudaFuncSetAttribute(gemm_fp16_kernel, cudaFuncAttributeMaxDynamicSharedMemorySize, GEMM_SMEM_BYTES);
        cudaFuncSetAttribute(attn_kernel,      cudaFuncAttributeMaxDynamicSharedMemorySize, ATT_SMEM_BYTES);
        inited = 1;
    }

    dim3 gg(GN/128, GM/128);
    const int xblks = (GM*GK/4)/256, wblks = (GN*GK/4)/256;

    // Q projection (1/sqrt(64) baked in): hi+lo out
    split_x_kernel<<<xblks, 256>>>(q, xhi, xlo, GM*GK/4);
    conv_w_kernel<<<wblks, 256>>>(Wq, whi, GN*GK/4);
    gemm_fp16_kernel<<<gg, 256, GEMM_SMEM_BYTES>>>(xhi, xlo, whi, bq, nullptr, qhh, qhl, 0.125f, 1);
    // K projection: hi only
    split_x_kernel<<<xblks, 256>>>(k, xhi, xlo, GM*GK/4);
    conv_w_kernel<<<wblks, 256>>>(Wk, whi, GN*GK/4);
    gemm_fp16_kernel<<<gg, 256, GEMM_SMEM_BYTES>>>(xhi, xlo, whi, bk, nullptr, khh, nullptr, 1.0f, 2);
    // V projection: hi only, then transpose
    split_x_kernel<<<xblks, 256>>>(v, xhi, xlo, GM*GK/4);
    conv_w_kernel<<<wblks, 256>>>(Wv, whi, GN*GK/4);
    gemm_fp16_kernel<<<gg, 256, GEMM_SMEM_BYTES>>>(xhi, xlo, whi, bv, nullptr, vhh, nullptr, 1.0f, 2);
    vtrans_kernel<<<dim3(SEQ/128, BHN), 256>>>(vhh, vth);

    // attention (writes ctx into xhi/xlo)
    float* align_out = outp + (size_t)BATCH * SEQ * DIMN;
    attn_kernel<<<dim3(SEQ/TQ, BHN), 512, ATT_SMEM_BYTES>>>(rpe_w, align_out);

    // output projection
    conv_w_kernel<<<wblks, 256>>>(Wo, whi, GN*GK/4);
    gemm_fp16_kernel<<<gg, 256, GEMM_SMEM_BYTES>>>(xhi, xlo, whi, bo, outp, nullptr, nullptr, 1.0f, 0);
}

// round 9
// speedup vs baseline: 1.0805x; 1.0805x over previous
#include <cuda_runtime.h>
#include <cuda_fp16.h>
#include <cstdint>
#include <cstddef>

#define DIMN   1024
#define HEADS  16
#define HDIM   64
#define BATCH  4
#define SEQ    1024
#define BHN    (BATCH*HEADS)
#define NB     33

#define GM (BATCH*SEQ)
#define GN DIMN
#define GK DIMN

typedef __half h16;

// ---------------- scratch (device globals; no allocation allowed) ----------
__device__ h16 g_qxh[GM*GK];          // q input split hi
__device__ h16 g_qxl[GM*GK];          // q input split lo
__device__ h16 g_kxh[GM*GK];          // k input hi only
__device__ h16 g_vxh[GM*GK];          // v input hi only
__device__ h16 g_w[4*(size_t)GN*GK];  // Wq,Wk,Wv,Wo fp16
__device__ h16 g_qhh[BHN*SEQ*HDIM];
__device__ h16 g_qhl[BHN*SEQ*HDIM];
__device__ h16 g_khh[BHN*SEQ*HDIM];
__device__ h16 g_vhh[BHN*SEQ*HDIM];
__device__ h16 g_cxh[GM*DIMN];        // attn ctx hi
__device__ h16 g_cxl[GM*DIMN];        // attn ctx lo

// ---------------- helpers ---------------------------------------------------
__device__ __forceinline__ void mma16h(float* d, const uint32_t* a, const uint32_t* b) {
    asm volatile(
        "mma.sync.aligned.m16n8k16.row.col.f32.f16.f16.f32 "
        "{%0,%1,%2,%3},{%4,%5,%6,%7},{%8,%9},{%0,%1,%2,%3};"
        : "+f"(d[0]), "+f"(d[1]), "+f"(d[2]), "+f"(d[3])
        : "r"(a[0]), "r"(a[1]), "r"(a[2]), "r"(a[3]), "r"(b[0]), "r"(b[1]));
}
__device__ __forceinline__ void ldsm4(uint32_t* r, uint32_t addr) {
    asm volatile("ldmatrix.sync.aligned.m8n8.x4.shared.b16 {%0,%1,%2,%3}, [%4];"
        : "=r"(r[0]), "=r"(r[1]), "=r"(r[2]), "=r"(r[3]) : "r"(addr));
}
__device__ __forceinline__ void ldsm2t(uint32_t* r, uint32_t addr) {
    asm volatile("ldmatrix.sync.aligned.m8n8.x2.trans.shared.b16 {%0,%1}, [%2];"
        : "=r"(r[0]), "=r"(r[1]) : "r"(addr));
}
__device__ __forceinline__ uint32_t smem_u32(const void* p) {
    uint32_t r;
    asm("{ .reg .u64 t; cvta.to.shared.u64 t, %1; cvt.u32.u64 %0, t; }" : "=r"(r) : "l"(p));
    return r;
}
__device__ __forceinline__ uint32_t pack2h(float x, float y) {
    uint32_t r;
    h16 a = __float2half_rn(x), b = __float2half_rn(y);
    asm("mov.b32 %0, {%1, %2};" : "=r"(r) : "h"(*(uint16_t*)&a), "h"(*(uint16_t*)&b));
    return r;
}
#define CP16(dst_u32, src_ptr) \
    asm volatile("cp.async.cg.shared.global [%0], [%1], 16;" :: "r"(dst_u32), "l"(src_ptr))
#define CP_COMMIT() asm volatile("cp.async.commit_group;")
#define CP_WAIT1()  asm volatile("cp.async.wait_group 1;")
#define CP_WAIT0()  asm volatile("cp.async.wait_group 0;")

// ---------------- prep: all splits + conversions in one launch --------------
// job 0: split q -> qxh/qxl; job 1: k -> kxh; job 2: v -> vxh;
// jobs 3-6: Wq,Wk,Wv,Wo -> g_w[job-3]
__global__ __launch_bounds__(256)
void prep_kernel(const float* __restrict__ q, const float* __restrict__ k,
                 const float* __restrict__ v, const float* __restrict__ Wq,
                 const float* __restrict__ Wk, const float* __restrict__ Wv,
                 const float* __restrict__ Wo)
{
    const int job = blockIdx.y;
    const int i = blockIdx.x * 256 + threadIdx.x;
    if (job == 0) {
        if (i >= GM*GK/4) return;
        float4 f4 = ((const float4*)q)[i];
        float f[4] = {f4.x, f4.y, f4.z, f4.w};
        h16 h[4], l[4];
        #pragma unroll
        for (int j = 0; j < 4; j++) {
            h[j] = __float2half_rn(f[j]);
            l[j] = __float2half_rn(f[j] - __half2float(h[j]));
        }
        *(uint2*)&g_qxh[(size_t)i*4] = *(uint2*)h;
        *(uint2*)&g_qxl[(size_t)i*4] = *(uint2*)l;
    } else if (job <= 2) {
        if (i >= GM*GK/4) return;
        const float* s = (job == 1) ? k : v;
        h16* d = (job == 1) ? g_kxh : g_vxh;
        float4 f4 = ((const float4*)s)[i];
        h16 h[4] = { __float2half_rn(f4.x), __float2half_rn(f4.y),
                     __float2half_rn(f4.z), __float2half_rn(f4.w) };
        *(uint2*)&d[(size_t)i*4] = *(uint2*)h;
    } else {
        if (i >= GN*GK/4) return;
        const float* s = (job == 3) ? Wq : (job == 4) ? Wk : (job == 5) ? Wv : Wo;
        h16* d = g_w + (size_t)(job - 3) * GN * GK;
        float4 f4 = ((const float4*)s)[i];
        h16 h[4] = { __float2half_rn(f4.x), __float2half_rn(f4.y),
                     __float2half_rn(f4.z), __float2half_rn(f4.w) };
        *(uint2*)&d[(size_t)i*4] = *(uint2*)h;
    }
}

// ---------------- GEMM core: C = X @ W^T + bias, *scale ---------------------
// 128x128 tile, BK=32, cp.async double-buffered, LDSM fragments.
// mode 0: fp32 out. mode 1: head layout hi+lo. mode 2: head layout hi only.
#define TILEB  (128*80)
#define STAGEB (3*TILEB)
#define GEMM_SMEM_BYTES (2*STAGEB)

__device__ __forceinline__
void gemm_body(const h16* __restrict__ Xh, const h16* __restrict__ Xl,
               const h16* __restrict__ Wh, const float* __restrict__ bias,
               float* __restrict__ outf, h16* __restrict__ oh, h16* __restrict__ ol,
               float scale, int mode, int has_lo, char* gsm)
{
    const uint32_t sb = smem_u32(gsm);
    const int tid  = threadIdx.x;
    const int m0   = blockIdx.y * 128;
    const int n0   = blockIdx.x * 128;
    const int warp = tid >> 5, lane = tid & 31;
    const int gid  = lane >> 2, tig = lane & 3;
    const int wm   = warp >> 2, wn = warp & 3;

    const uint32_t aoffB = (uint32_t)((lane & 15)*80 + ((lane >> 4) << 4));
    const uint32_t boffB = (uint32_t)(((lane & 7) + ((lane >> 4) << 3))*80 + (((lane >> 3) & 1) << 4));

    float acc[4][4][4];
    #pragma unroll
    for (int i = 0; i < 4; i++)
        #pragma unroll
        for (int j = 0; j < 4; j++)
            #pragma unroll
            for (int e = 0; e < 4; e++) acc[i][j][e] = 0.f;

    auto fill = [&](int s) {
        const int k0 = s * 32;
        const uint32_t bU = sb + (uint32_t)(s & 1) * STAGEB;
        #pragma unroll
        for (int it = 0; it < 2; it++) {
            int idx = tid + it * 256;
            int r = idx >> 2, c = idx & 3;
            uint32_t d = (uint32_t)(r*80 + c*16);
            CP16(bU + d,           Xh + (size_t)(m0 + r)*GK + k0 + c*8);
            CP16(bU + 2*TILEB + d, Wh + (size_t)(n0 + r)*GK + k0 + c*8);
            if (has_lo) CP16(bU + TILEB + d, Xl + (size_t)(m0 + r)*GK + k0 + c*8);
        }
        CP_COMMIT();
    };

    fill(0);
    fill(1);
    for (int t = 0; t < 32; t++) {
        if (t < 31) CP_WAIT1(); else CP_WAIT0();
        __syncthreads();

        const uint32_t st  = sb + (uint32_t)(t & 1) * STAGEB;
        #pragma unroll
        for (int kkb = 0; kkb < 64; kkb += 32) {
            uint32_t bf[2][4];
            ldsm4(bf[0], st + 2*TILEB + (uint32_t)((wn*32     )*80) + boffB + kkb);
            ldsm4(bf[1], st + 2*TILEB + (uint32_t)((wn*32 + 16)*80) + boffB + kkb);
            #pragma unroll
            for (int i = 0; i < 4; i++) {
                uint32_t rb = (uint32_t)((wm*64 + i*16)*80) + aoffB + kkb;
                uint32_t ah[4], al[4];
                ldsm4(ah, st + rb);
                if (has_lo) ldsm4(al, st + TILEB + rb);
                #pragma unroll
                for (int j = 0; j < 4; j++) {
                    const uint32_t* b = &bf[j >> 1][(j & 1)*2];
                    mma16h(acc[i][j], ah, b);
                    if (has_lo) mma16h(acc[i][j], al, b);
                }
            }
        }
        __syncthreads();
        if (t + 2 < 32) fill(t + 2);
    }

    #pragma unroll
    for (int i = 0; i < 4; i++) {
        int r0 = m0 + wm*64 + i*16 + gid;
        #pragma unroll
        for (int j = 0; j < 4; j++) {
            int nc = n0 + wn*32 + j*8 + 2*tig;
            float b0 = bias[nc], b1 = bias[nc + 1];
            float v00 = (acc[i][j][0] + b0) * scale;
            float v01 = (acc[i][j][1] + b1) * scale;
            float v10 = (acc[i][j][2] + b0) * scale;
            float v11 = (acc[i][j][3] + b1) * scale;
            if (mode == 0) {
                *(float2*)(outf + (size_t)r0 * GN + nc)       = make_float2(v00, v01);
                *(float2*)(outf + (size_t)(r0 + 8) * GN + nc) = make_float2(v10, v11);
            } else {
                int h = nc >> 6, d = nc & 63;
                int b0i = r0 >> 10, t0 = r0 & (SEQ - 1);
                int b1i = (r0 + 8) >> 10, t1 = (r0 + 8) & (SEQ - 1);
                size_t a0 = ((size_t)((b0i*HEADS + h)*SEQ + t0))*HDIM + d;
                size_t a1 = ((size_t)((b1i*HEADS + h)*SEQ + t1))*HDIM + d;
                *(uint32_t*)&oh[a0] = pack2h(v00, v01);
                *(uint32_t*)&oh[a1] = pack2h(v10, v11);
                if (mode == 1) {
                    h16 h00 = __float2half_rn(v00), h01 = __float2half_rn(v01);
                    h16 h10 = __float2half_rn(v10), h11 = __float2half_rn(v11);
                    *(uint32_t*)&ol[a0] = pack2h(v00 - __half2float(h00), v01 - __half2float(h01));
                    *(uint32_t*)&ol[a1] = pack2h(v10 - __half2float(h10), v11 - __half2float(h11));
                }
            }
        }
    }
}

// batched QKV projections: z=0 Q (hi+lo out, scale 1/8), z=1 K, z=2 V
__global__ __launch_bounds__(256, 2)
void qkv_gemm_kernel(const float* __restrict__ bq, const float* __restrict__ bk,
                     const float* __restrict__ bv)
{
    extern __shared__ char gsm[];
    const int z = blockIdx.z;
    if (z == 0)
        gemm_body(g_qxh, g_qxl, g_w,            bq, nullptr, g_qhh, g_qhl, 0.125f, 1, 1, gsm);
    else if (z == 1)
        gemm_body(g_kxh, nullptr, g_w + (size_t)GN*GK,   bk, nullptr, g_khh, nullptr, 1.0f, 2, 0, gsm);
    else
        gemm_body(g_vxh, nullptr, g_w + 2*(size_t)GN*GK, bv, nullptr, g_vhh, nullptr, 1.0f, 2, 0, gsm);
}

__global__ __launch_bounds__(256, 2)
void out_gemm_kernel(const float* __restrict__ bo, float* __restrict__ outp)
{
    extern __shared__ char gsm[];
    gemm_body(g_cxh, g_cxl, g_w + 3*(size_t)GN*GK, bo, outp, nullptr, nullptr, 1.0f, 0, 1, gsm);
}

// ---------------- attention kernel ------------------------------------------
#define TQ   32
#define ESTR 1036
#define B_E     0
#define B_QH    (TQ*ESTR*4)
#define B_QL    (B_QH + TQ*144)
#define B_KV    (B_QL + TQ*144)
#define B_RWV   (B_KV + 2*18432)
#define B_PROJ  (B_RWV + NB*64*4)
#define B_SROW  (B_PROJ + TQ*NB*4)
#define B_RPECV (B_SROW + TQ*NB*4)
#define ATT_SMEM_BYTES (B_RPECV + TQ*64*4)

__device__ __forceinline__ int rpe_clip(int dd) {
    dd = dd < -16 ? -16 : (dd > 16 ? 16 : dd);
    return dd + 16;
}

__global__ __launch_bounds__(512)
void attn_kernel(const float* __restrict__ rpe_w, float* __restrict__ align_out)
{
    extern __shared__ char smc[];
    float* e     = (float*)smc;
    float* rwv   = (float*)(smc + B_RWV);
    float* proj  = (float*)(smc + B_PROJ);
    float* srow  = (float*)(smc + B_SROW);
    float* rpecv = (float*)(smc + B_RPECV);

    const uint32_t sbase = smem_u32(smc);
    const uint32_t sE = sbase, sQH = sbase + B_QH, sQL = sbase + B_QL, sKV = sbase + B_KV;

    const int bhid = blockIdx.y;
    const int q0   = blockIdx.x * TQ;
    const int tid  = threadIdx.x;
    const int warp = tid >> 5, lane = tid & 31;
    const int gid  = lane >> 2, tig = lane & 3;

    // ---- prologue: Q hi/lo tiles, rpe_v table ----
    {
        int r = (tid & 255) >> 3, c = tid & 7;
        const h16* src = (tid < 256) ? g_qhh : g_qhl;
        char* dst = smc + ((tid < 256) ? B_QH : B_QL);
        *(uint4*)(dst + r*144 + c*16) =
            *(const uint4*)&src[((size_t)bhid*SEQ + q0 + r)*HDIM + c*8];
    }
    for (int i = tid; i < NB*64; i += 512) {
        int t = i >> 6, d = i & 63;
        rwv[i] = rpe_w[t*128 + 64 + d];
    }
    __syncthreads();

    // proj[q][t] = qh[q] . rpe_w[t, 0:64]
    {
        const h16* qh16 = (const h16*)(smc + B_QH);
        const h16* ql16 = (const h16*)(smc + B_QL);
        for (int i = tid; i < TQ*NB; i += 512) {
            int q = i / NB, t = i - q*NB;
            const float* rp = rpe_w + t*128;
            float s = 0.f;
            #pragma unroll 16
            for (int d = 0; d < 64; d++)
                s += (__half2float(qh16[q*72 + d]) + __half2float(ql16[q*72 + d])) * __ldg(&rp[d]);
            proj[i] = s;
        }
    }

    // ---- hoist Q fragments ----
    const int mS = warp & 1;
    const int np = warp >> 1;
    const uint32_t aoffQ = (uint32_t)((lane & 15)*144 + ((lane >> 4) << 4));
    const uint32_t boffS = (uint32_t)(((lane & 7) + ((lane >> 4) << 3))*144 + (((lane >> 3) & 1) << 4));
    uint32_t qhf[4][4], qlf[4][4];
    {
        uint32_t qb = (uint32_t)(mS*16*144) + aoffQ;
        #pragma unroll
        for (int ks = 0; ks < 4; ks++) {
            ldsm4(qhf[ks], sQH + qb + ks*32);
            ldsm4(qlf[ks], sQL + qb + ks*32);
        }
    }

    // ---- S = Q K^T + rpe_q ----
    auto fillK = [&](int ktI) {
        uint32_t bU = sKV + (uint32_t)(ktI & 1)*18432;
        const h16* kb = g_khh + ((size_t)bhid*SEQ + ktI*128)*HDIM;
        #pragma unroll
        for (int it = 0; it < 2; it++) {
            int idx = tid + it*512;
            int r = idx >> 3, c = idx & 7;
            CP16(bU + (uint32_t)(r*144 + c*16), kb + (size_t)r*64 + c*8);
        }
        CP_COMMIT();
    };

    fillK(0);
    for (int ktI = 0; ktI < 8; ktI++) {
        if (ktI < 7) { fillK(ktI + 1); CP_WAIT1(); } else CP_WAIT0();
        __syncthreads();

        uint32_t KU = sKV + (uint32_t)(ktI & 1)*18432 + (uint32_t)(np*16*144);
        float acc[2][4] = {{0.f,0.f,0.f,0.f},{0.f,0.f,0.f,0.f}};
        #pragma unroll
        for (int ks = 0; ks < 4; ks++) {
            uint32_t bf[4];
            ldsm4(bf, KU + boffS + ks*32);
            mma16h(acc[0], qhf[ks], bf);
            mma16h(acc[0], qlf[ks], bf);
            mma16h(acc[1], qhf[ks], bf + 2);
            mma16h(acc[1], qlf[ks], bf + 2);
        }
        int qA = mS*16 + gid, qB = qA + 8;
        int qgA = q0 + qA, qgB = q0 + qB;
        int kt = ktI * 128;
        #pragma unroll
        for (int jj = 0; jj < 2; jj++) {
            int k0c = kt + np*16 + jj*8 + 2*tig;
            e[qA*ESTR + k0c    ] = acc[jj][0] + proj[qA*NB + rpe_clip(qgA - k0c)];
            e[qA*ESTR + k0c + 1] = acc[jj][1] + proj[qA*NB + rpe_clip(qgA - k0c - 1)];
            e[qB*ESTR + k0c    ] = acc[jj][2] + proj[qB*NB + rpe_clip(qgB - k0c)];
            e[qB*ESTR + k0c + 1] = acc[jj][3] + proj[qB*NB + rpe_clip(qgB - k0c - 1)];
        }
        __syncthreads();
    }

    // prefetch V tiles 0,1 (same [t][d] layout as K; overlaps softmax)
    auto fillV = [&](int ktI) {
        uint32_t bU = sKV + (uint32_t)(ktI & 1)*18432;
        const h16* vb = g_vhh + ((size_t)bhid*SEQ + ktI*128)*HDIM;
        #pragma unroll
        for (int it = 0; it < 2; it++) {
            int idx = tid + it*512;
            int r = idx >> 3, c = idx & 7;
            CP16(bU + (uint32_t)(r*144 + c*16), vb + (size_t)r*64 + c*8);
        }
        CP_COMMIT();
    };
    fillV(0);
    fillV(1);

    // ---- softmax + alignment + buckets + P fp16 pack ----
    for (int q = warp*2; q < warp*2 + 2; q++) {
        int qglob = q0 + q;
        float* row = e + q*ESTR;
        float ev[32];
        float mx = -1e30f;
        #pragma unroll
        for (int i = 0; i < 8; i++) {
            float4 vv = *(float4*)&row[i*128 + lane*4];
            ev[i*4+0] = vv.x; ev[i*4+1] = vv.y; ev[i*4+2] = vv.z; ev[i*4+3] = vv.w;
            mx = fmaxf(mx, fmaxf(fmaxf(vv.x, vv.y), fmaxf(vv.z, vv.w)));
        }
        #pragma unroll
        for (int o = 16; o; o >>= 1) mx = fmaxf(mx, __shfl_xor_sync(0xffffffffu, mx, o));
        float sum = 0.f;
        #pragma unroll
        for (int i = 0; i < 32; i++) { ev[i] = __expf(ev[i] - mx); sum += ev[i]; }
        #pragma unroll
        for (int o = 16; o; o >>= 1) sum += __shfl_xor_sync(0xffffffffu, sum, o);
        float inv = 1.f / sum;

        if (lane) srow[q*NB + lane] = 0.f;
        __syncwarp();

        float slo = 0.f, shi = 0.f;
        h16* hid = (h16*)row;
        h16* lod = hid + 1024;
        float* arow = align_out + ((size_t)(bhid * SEQ + qglob)) * SEQ;
        #pragma unroll
        for (int i = 0; i < 8; i++) {
            int k0 = i*128 + lane*4;
            float p[4];
            #pragma unroll
            for (int c = 0; c < 4; c++) p[c] = ev[i*4 + c] * inv;
            *(float4*)&arow[k0] = make_float4(p[0], p[1], p[2], p[3]);
            h16 ph[4];
            #pragma unroll
            for (int c = 0; c < 4; c++) ph[c] = __float2half_rn(p[c]);
            *(uint2*)&hid[k0] = *(uint2*)ph;
            h16 pl[4];
            #pragma unroll
            for (int c = 0; c < 4; c++) pl[c] = __float2half_rn(p[c] - __half2float(ph[c]));
            *(uint2*)&lod[k0] = *(uint2*)pl;
            #pragma unroll
            for (int c = 0; c < 4; c++) {
                int dd = qglob - (k0 + c);
                if (dd >= 16)       slo += p[c];
                else if (dd <= -16) shi += p[c];
                else                srow[q*NB + dd + 16] = p[c];
            }
        }
        #pragma unroll
        for (int o = 16; o; o >>= 1) {
            slo += __shfl_xor_sync(0xffffffffu, slo, o);
            shi += __shfl_xor_sync(0xffffffffu, shi, o);
        }
        if (lane == 0) { srow[q*NB + 32] = slo; srow[q*NB + 0] = shi; }
    }
    __syncthreads();

    // ---- rpecv[32][64] = srow @ rpe_v ----
    for (int i = tid; i < TQ*64; i += 512) {
        int q = i >> 6, d = i & 63;
        float s = 0.f;
        #pragma unroll
        for (int t = 0; t < NB; t++) s += srow[q*NB + t] * rwv[t*64 + d];
        rpecv[i] = s;
    }

    // ---- PV: P (fp16 hi/lo packed in e) x V via trans-LDSM ----
    const int mP = warp & 1;
    const int nt = warp >> 1;
    const uint32_t aoffP = (uint32_t)((lane & 15)*(ESTR*4) + ((lane >> 4) << 4));
    float accP[4] = {0.f, 0.f, 0.f, 0.f};
    for (int ktI = 0; ktI < 8; ktI++) {
        if (ktI < 7) CP_WAIT1(); else CP_WAIT0();
        __syncthreads();
        uint32_t VU = sKV + (uint32_t)(ktI & 1)*18432;
        uint32_t PB = sE + (uint32_t)(mP*16*(ESTR*4)) + aoffP + (uint32_t)(ktI*256);
        #pragma unroll
        for (int ks = 0; ks < 8; ks++) {
            uint32_t ph[4], pl[4], bv[2];
            ldsm4(ph, PB + ks*32);
            ldsm4(pl, PB + 2048 + ks*32);
            ldsm2t(bv, VU + (uint32_t)((ks*16 + (lane & 15))*144 + nt*16));
            mma16h(accP, ph, bv);
            mma16h(accP, pl, bv);
        }
        __syncthreads();
        if (ktI + 2 < 8) fillV(ktI + 2);
    }

    // ---- epilogue: + rpecv, write ctx fp16 hi/lo ----
    {
        int qA = mP*16 + gid, qB = qA + 8;
        int d0 = nt*8 + 2*tig;
        int b = bhid >> 4, h = bhid & 15;
        float v00 = accP[0] + rpecv[qA*64 + d0];
        float v01 = accP[1] + rpecv[qA*64 + d0 + 1];
        float v10 = accP[2] + rpecv[qB*64 + d0];
        float v11 = accP[3] + rpecv[qB*64 + d0 + 1];
        size_t a0 = (size_t)(b*SEQ + q0 + qA)*DIMN + h*HDIM + d0;
        size_t a1 = (size_t)(b*SEQ + q0 + qB)*DIMN + h*HDIM + d0;
        h16 h00 = __float2half_rn(v00), h01 = __float2half_rn(v01);
        h16 h10 = __float2half_rn(v10), h11 = __float2half_rn(v11);
        *(uint32_t*)&g_cxh[a0] = pack2h(v00, v01);
        *(uint32_t*)&g_cxh[a1] = pack2h(v10, v11);
        *(uint32_t*)&g_cxl[a0] = pack2h(v00 - __half2float(h00), v01 - __half2float(h01));
        *(uint32_t*)&g_cxl[a1] = pack2h(v10 - __half2float(h10), v11 - __half2float(h11));
    }
}

// ---------------- launch ---------------------------------------------------
extern "C" void kernel_launch(void* const* d_in, const int* in_sizes, int n_in,
                              void* d_out, int out_size)
{
    const float* q     = (const float*)d_in[0];
    const float* k     = (const float*)d_in[1];
    const float* v     = (const float*)d_in[2];
    const float* Wq    = (const float*)d_in[3];
    const float* bq    = (const float*)d_in[4];
    const float* Wk    = (const float*)d_in[5];
    const float* bk    = (const float*)d_in[6];
    const float* Wv    = (const float*)d_in[7];
    const float* bv    = (const float*)d_in[8];
    const float* rpe_w = (const float*)d_in[9];
    const float* Wo    = (const float*)d_in[10];
    const float* bo    = (const float*)d_in[11];
    float* outp = (float*)d_out;

    static int inited = 0;
    if (!inited) {
        cudaFuncSetAttribute(qkv_gemm_kernel, cudaFuncAttributeMaxDynamicSharedMemorySize, GEMM_SMEM_BYTES);
        cudaFuncSetAttribute(out_gemm_kernel, cudaFuncAttributeMaxDynamicSharedMemorySize, GEMM_SMEM_BYTES);
        cudaFuncSetAttribute(attn_kernel,     cudaFuncAttributeMaxDynamicSharedMemorySize, ATT_SMEM_BYTES);
        inited = 1;
    }

    prep_kernel<<<dim3(GM*GK/4/256, 7), 256>>>(q, k, v, Wq, Wk, Wv, Wo);
    qkv_gemm_kernel<<<dim3(GN/128, GM/128, 3), 256, GEMM_SMEM_BYTES>>>(bq, bk, bv);

    float* align_out = outp + (size_t)BATCH * SEQ * DIMN;
    attn_kernel<<<dim3(SEQ/TQ, BHN), 512, ATT_SMEM_BYTES>>>(rpe_w, align_out);

    out_gemm_kernel<<<dim3(GN/128, GM/128), 256, GEMM_SMEM_BYTES>>>(bo, outp);
}

// round 10
// speedup vs baseline: 1.0820x; 1.0015x over previous
#include <cuda_runtime.h>
#include <cuda_fp16.h>
#include <cstdint>
#include <cstddef>

#define DIMN   1024
#define HEADS  16
#define HDIM   64
#define BATCH  4
#define SEQ    1024
#define BHN    (BATCH*HEADS)
#define NB     33

#define GM (BATCH*SEQ)
#define GN DIMN
#define GK DIMN

typedef __half h16;

// ---------------- scratch (device globals; no allocation allowed) ----------
__device__ h16 g_qxh[GM*GK];          // q input split hi
__device__ h16 g_qxl[GM*GK];          // q input split lo
__device__ h16 g_kxh[GM*GK];          // k input hi only
__device__ h16 g_vxh[GM*GK];          // v input hi only
__device__ h16 g_w[4*(size_t)GN*GK];  // Wq,Wk,Wv,Wo fp16
__device__ h16 g_qhh[BHN*SEQ*HDIM];
__device__ h16 g_qhl[BHN*SEQ*HDIM];
__device__ h16 g_khh[BHN*SEQ*HDIM];
__device__ h16 g_vhh[BHN*SEQ*HDIM];
__device__ h16 g_cxh[GM*DIMN];        // attn ctx hi
__device__ h16 g_cxl[GM*DIMN];        // attn ctx lo

// ---------------- helpers ---------------------------------------------------
__device__ __forceinline__ void mma16h(float* d, const uint32_t* a, const uint32_t* b) {
    asm volatile(
        "mma.sync.aligned.m16n8k16.row.col.f32.f16.f16.f32 "
        "{%0,%1,%2,%3},{%4,%5,%6,%7},{%8,%9},{%0,%1,%2,%3};"
        : "+f"(d[0]), "+f"(d[1]), "+f"(d[2]), "+f"(d[3])
        : "r"(a[0]), "r"(a[1]), "r"(a[2]), "r"(a[3]), "r"(b[0]), "r"(b[1]));
}
__device__ __forceinline__ void ldsm4(uint32_t* r, uint32_t addr) {
    asm volatile("ldmatrix.sync.aligned.m8n8.x4.shared.b16 {%0,%1,%2,%3}, [%4];"
        : "=r"(r[0]), "=r"(r[1]), "=r"(r[2]), "=r"(r[3]) : "r"(addr));
}
__device__ __forceinline__ void ldsm2t(uint32_t* r, uint32_t addr) {
    asm volatile("ldmatrix.sync.aligned.m8n8.x2.trans.shared.b16 {%0,%1}, [%2];"
        : "=r"(r[0]), "=r"(r[1]) : "r"(addr));
}
__device__ __forceinline__ uint32_t smem_u32(const void* p) {
    uint32_t r;
    asm("{ .reg .u64 t; cvta.to.shared.u64 t, %1; cvt.u32.u64 %0, t; }" : "=r"(r) : "l"(p));
    return r;
}
__device__ __forceinline__ uint32_t pack2h(float x, float y) {
    uint32_t r;
    h16 a = __float2half_rn(x), b = __float2half_rn(y);
    asm("mov.b32 %0, {%1, %2};" : "=r"(r) : "h"(*(uint16_t*)&a), "h"(*(uint16_t*)&b));
    return r;
}
#define CP16(dst_u32, src_ptr) \
    asm volatile("cp.async.cg.shared.global [%0], [%1], 16;" :: "r"(dst_u32), "l"(src_ptr))
#define CP_COMMIT() asm volatile("cp.async.commit_group;")
#define CP_WAIT1()  asm volatile("cp.async.wait_group 1;")
#define CP_WAIT0()  asm volatile("cp.async.wait_group 0;")

// ---------------- prep: all splits + conversions in one launch --------------
// job 0: split q -> qxh/qxl; job 1: k -> kxh; job 2: v -> vxh;
// jobs 3-6: Wq,Wk,Wv,Wo -> g_w[job-3]
__global__ __launch_bounds__(256)
void prep_kernel(const float* __restrict__ q, const float* __restrict__ k,
                 const float* __restrict__ v, const float* __restrict__ Wq,
                 const float* __restrict__ Wk, const float* __restrict__ Wv,
                 const float* __restrict__ Wo)
{
    const int job = blockIdx.y;
    const int i = blockIdx.x * 256 + threadIdx.x;
    if (job == 0) {
        if (i >= GM*GK/4) return;
        float4 f4 = ((const float4*)q)[i];
        float f[4] = {f4.x, f4.y, f4.z, f4.w};
        h16 h[4], l[4];
        #pragma unroll
        for (int j = 0; j < 4; j++) {
            h[j] = __float2half_rn(f[j]);
            l[j] = __float2half_rn(f[j] - __half2float(h[j]));
        }
        *(uint2*)&g_qxh[(size_t)i*4] = *(uint2*)h;
        *(uint2*)&g_qxl[(size_t)i*4] = *(uint2*)l;
    } else if (job <= 2) {
        if (i >= GM*GK/4) return;
        const float* s = (job == 1) ? k : v;
        h16* d = (job == 1) ? g_kxh : g_vxh;
        float4 f4 = ((const float4*)s)[i];
        h16 h[4] = { __float2half_rn(f4.x), __float2half_rn(f4.y),
                     __float2half_rn(f4.z), __float2half_rn(f4.w) };
        *(uint2*)&d[(size_t)i*4] = *(uint2*)h;
    } else {
        if (i >= GN*GK/4) return;
        const float* s = (job == 3) ? Wq : (job == 4) ? Wk : (job == 5) ? Wv : Wo;
        h16* d = g_w + (size_t)(job - 3) * GN * GK;
        float4 f4 = ((const float4*)s)[i];
        h16 h[4] = { __float2half_rn(f4.x), __float2half_rn(f4.y),
                     __float2half_rn(f4.z), __float2half_rn(f4.w) };
        *(uint2*)&d[(size_t)i*4] = *(uint2*)h;
    }
}

// ---------------- GEMM core: C = X @ W^T + bias, *scale ---------------------
// 128x128 tile, BK=32, cp.async double-buffered, LDSM fragments.
// mode 0: fp32 out. mode 1: head layout hi+lo. mode 2: head layout hi only.
#define TILEB  (128*80)
#define STAGEB (3*TILEB)
#define GEMM_SMEM_BYTES (2*STAGEB)

__device__ __forceinline__
void gemm_body(const h16* __restrict__ Xh, const h16* __restrict__ Xl,
               const h16* __restrict__ Wh, const float* __restrict__ bias,
               float* __restrict__ outf, h16* __restrict__ oh, h16* __restrict__ ol,
               float scale, int mode, int has_lo, char* gsm)
{
    const uint32_t sb = smem_u32(gsm);
    const int tid  = threadIdx.x;
    const int m0   = blockIdx.y * 128;
    const int n0   = blockIdx.x * 128;
    const int warp = tid >> 5, lane = tid & 31;
    const int gid  = lane >> 2, tig = lane & 3;
    const int wm   = warp >> 2, wn = warp & 3;

    const uint32_t aoffB = (uint32_t)((lane & 15)*80 + ((lane >> 4) << 4));
    const uint32_t boffB = (uint32_t)(((lane & 7) + ((lane >> 4) << 3))*80 + (((lane >> 3) & 1) << 4));

    float acc[4][4][4];
    #pragma unroll
    for (int i = 0; i < 4; i++)
        #pragma unroll
        for (int j = 0; j < 4; j++)
            #pragma unroll
            for (int e = 0; e < 4; e++) acc[i][j][e] = 0.f;

    auto fill = [&](int s) {
        const int k0 = s * 32;
        const uint32_t bU = sb + (uint32_t)(s & 1) * STAGEB;
        #pragma unroll
        for (int it = 0; it < 2; it++) {
            int idx = tid + it * 256;
            int r = idx >> 2, c = idx & 3;
            uint32_t d = (uint32_t)(r*80 + c*16);
            CP16(bU + d,           Xh + (size_t)(m0 + r)*GK + k0 + c*8);
            CP16(bU + 2*TILEB + d, Wh + (size_t)(n0 + r)*GK + k0 + c*8);
            if (has_lo) CP16(bU + TILEB + d, Xl + (size_t)(m0 + r)*GK + k0 + c*8);
        }
        CP_COMMIT();
    };

    fill(0);
    fill(1);
    for (int t = 0; t < 32; t++) {
        if (t < 31) CP_WAIT1(); else CP_WAIT0();
        __syncthreads();

        const uint32_t st  = sb + (uint32_t)(t & 1) * STAGEB;
        #pragma unroll
        for (int kkb = 0; kkb < 64; kkb += 32) {
            uint32_t bf[2][4];
            ldsm4(bf[0], st + 2*TILEB + (uint32_t)((wn*32     )*80) + boffB + kkb);
            ldsm4(bf[1], st + 2*TILEB + (uint32_t)((wn*32 + 16)*80) + boffB + kkb);
            #pragma unroll
            for (int i = 0; i < 4; i++) {
                uint32_t rb = (uint32_t)((wm*64 + i*16)*80) + aoffB + kkb;
                uint32_t ah[4], al[4];
                ldsm4(ah, st + rb);
                if (has_lo) ldsm4(al, st + TILEB + rb);
                #pragma unroll
                for (int j = 0; j < 4; j++) {
                    const uint32_t* b = &bf[j >> 1][(j & 1)*2];
                    mma16h(acc[i][j], ah, b);
                    if (has_lo) mma16h(acc[i][j], al, b);
                }
            }
        }
        __syncthreads();
        if (t + 2 < 32) fill(t + 2);
    }

    #pragma unroll
    for (int i = 0; i < 4; i++) {
        int r0 = m0 + wm*64 + i*16 + gid;
        #pragma unroll
        for (int j = 0; j < 4; j++) {
            int nc = n0 + wn*32 + j*8 + 2*tig;
            float b0 = bias[nc], b1 = bias[nc + 1];
            float v00 = (acc[i][j][0] + b0) * scale;
            float v01 = (acc[i][j][1] + b1) * scale;
            float v10 = (acc[i][j][2] + b0) * scale;
            float v11 = (acc[i][j][3] + b1) * scale;
            if (mode == 0) {
                *(float2*)(outf + (size_t)r0 * GN + nc)       = make_float2(v00, v01);
                *(float2*)(outf + (size_t)(r0 + 8) * GN + nc) = make_float2(v10, v11);
            } else {
                int h = nc >> 6, d = nc & 63;
                int b0i = r0 >> 10, t0 = r0 & (SEQ - 1);
                int b1i = (r0 + 8) >> 10, t1 = (r0 + 8) & (SEQ - 1);
                size_t a0 = ((size_t)((b0i*HEADS + h)*SEQ + t0))*HDIM + d;
                size_t a1 = ((size_t)((b1i*HEADS + h)*SEQ + t1))*HDIM + d;
                *(uint32_t*)&oh[a0] = pack2h(v00, v01);
                *(uint32_t*)&oh[a1] = pack2h(v10, v11);
                if (mode == 1) {
                    h16 h00 = __float2half_rn(v00), h01 = __float2half_rn(v01);
                    h16 h10 = __float2half_rn(v10), h11 = __float2half_rn(v11);
                    *(uint32_t*)&ol[a0] = pack2h(v00 - __half2float(h00), v01 - __half2float(h01));
                    *(uint32_t*)&ol[a1] = pack2h(v10 - __half2float(h10), v11 - __half2float(h11));
                }
            }
        }
    }
}

// batched QKV projections: z=0 Q (hi+lo out, scale 1/8), z=1 K, z=2 V
__global__ __launch_bounds__(256, 2)
void qkv_gemm_kernel(const float* __restrict__ bq, const float* __restrict__ bk,
                     const float* __restrict__ bv)
{
    extern __shared__ char gsm[];
    const int z = blockIdx.z;
    if (z == 0)
        gemm_body(g_qxh, g_qxl, g_w,            bq, nullptr, g_qhh, g_qhl, 0.125f, 1, 1, gsm);
    else if (z == 1)
        gemm_body(g_kxh, nullptr, g_w + (size_t)GN*GK,   bk, nullptr, g_khh, nullptr, 1.0f, 2, 0, gsm);
    else
        gemm_body(g_vxh, nullptr, g_w + 2*(size_t)GN*GK, bv, nullptr, g_vhh, nullptr, 1.0f, 2, 0, gsm);
}

__global__ __launch_bounds__(256, 2)
void out_gemm_kernel(const float* __restrict__ bo, float* __restrict__ outp)
{
    extern __shared__ char gsm[];
    gemm_body(g_cxh, g_cxl, g_w + 3*(size_t)GN*GK, bo, outp, nullptr, nullptr, 1.0f, 0, 1, gsm);
}

// ---------------- attention kernel ------------------------------------------
#define TQ   32
#define ESTR 1036
#define B_E     0
#define B_QH    (TQ*ESTR*4)
#define B_QL    (B_QH + TQ*144)
#define B_KV    (B_QL + TQ*144)
#define B_RWV   (B_KV + 2*18432)
#define B_PROJ  (B_RWV + NB*64*4)
#define B_SROW  (B_PROJ + TQ*NB*4)
#define B_RPECV (B_SROW + TQ*NB*4)
#define ATT_SMEM_BYTES (B_RPECV + TQ*64*4)

__device__ __forceinline__ int rpe_clip(int dd) {
    dd = dd < -16 ? -16 : (dd > 16 ? 16 : dd);
    return dd + 16;
}

__global__ __launch_bounds__(512)
void attn_kernel(const float* __restrict__ rpe_w, float* __restrict__ align_out)
{
    extern __shared__ char smc[];
    float* e     = (float*)smc;
    float* rwv   = (float*)(smc + B_RWV);
    float* proj  = (float*)(smc + B_PROJ);
    float* srow  = (float*)(smc + B_SROW);
    float* rpecv = (float*)(smc + B_RPECV);

    const uint32_t sbase = smem_u32(smc);
    const uint32_t sE = sbase, sQH = sbase + B_QH, sQL = sbase + B_QL, sKV = sbase + B_KV;

    const int bhid = blockIdx.y;
    const int q0   = blockIdx.x * TQ;
    const int tid  = threadIdx.x;
    const int warp = tid >> 5, lane = tid & 31;
    const int gid  = lane >> 2, tig = lane & 3;

    // ---- prologue: Q hi/lo tiles, rpe_v table ----
    {
        int r = (tid & 255) >> 3, c = tid & 7;
        const h16* src = (tid < 256) ? g_qhh : g_qhl;
        char* dst = smc + ((tid < 256) ? B_QH : B_QL);
        *(uint4*)(dst + r*144 + c*16) =
            *(const uint4*)&src[((size_t)bhid*SEQ + q0 + r)*HDIM + c*8];
    }
    for (int i = tid; i < NB*64; i += 512) {
        int t = i >> 6, d = i & 63;
        rwv[i] = rpe_w[t*128 + 64 + d];
    }
    __syncthreads();

    // proj[q][t] = qh[q] . rpe_w[t, 0:64]
    {
        const h16* qh16 = (const h16*)(smc + B_QH);
        const h16* ql16 = (const h16*)(smc + B_QL);
        for (int i = tid; i < TQ*NB; i += 512) {
            int q = i / NB, t = i - q*NB;
            const float* rp = rpe_w + t*128;
            float s = 0.f;
            #pragma unroll 16
            for (int d = 0; d < 64; d++)
                s += (__half2float(qh16[q*72 + d]) + __half2float(ql16[q*72 + d])) * __ldg(&rp[d]);
            proj[i] = s;
        }
    }

    // ---- hoist Q fragments ----
    const int mS = warp & 1;
    const int np = warp >> 1;
    const uint32_t aoffQ = (uint32_t)((lane & 15)*144 + ((lane >> 4) << 4));
    const uint32_t boffS = (uint32_t)(((lane & 7) + ((lane >> 4) << 3))*144 + (((lane >> 3) & 1) << 4));
    uint32_t qhf[4][4], qlf[4][4];
    {
        uint32_t qb = (uint32_t)(mS*16*144) + aoffQ;
        #pragma unroll
        for (int ks = 0; ks < 4; ks++) {
            ldsm4(qhf[ks], sQH + qb + ks*32);
            ldsm4(qlf[ks], sQL + qb + ks*32);
        }
    }

    // ---- S = Q K^T + rpe_q ----
    auto fillK = [&](int ktI) {
        uint32_t bU = sKV + (uint32_t)(ktI & 1)*18432;
        const h16* kb = g_khh + ((size_t)bhid*SEQ + ktI*128)*HDIM;
        #pragma unroll
        for (int it = 0; it < 2; it++) {
            int idx = tid + it*512;
            int r = idx >> 3, c = idx & 7;
            CP16(bU + (uint32_t)(r*144 + c*16), kb + (size_t)r*64 + c*8);
        }
        CP_COMMIT();
    };

    fillK(0);
    for (int ktI = 0; ktI < 8; ktI++) {
        if (ktI < 7) { fillK(ktI + 1); CP_WAIT1(); } else CP_WAIT0();
        __syncthreads();

        uint32_t KU = sKV + (uint32_t)(ktI & 1)*18432 + (uint32_t)(np*16*144);
        float acc[2][4] = {{0.f,0.f,0.f,0.f},{0.f,0.f,0.f,0.f}};
        #pragma unroll
        for (int ks = 0; ks < 4; ks++) {
            uint32_t bf[4];
            ldsm4(bf, KU + boffS + ks*32);
            mma16h(acc[0], qhf[ks], bf);
            mma16h(acc[0], qlf[ks], bf);
            mma16h(acc[1], qhf[ks], bf + 2);
            mma16h(acc[1], qlf[ks], bf + 2);
        }
        int qA = mS*16 + gid, qB = qA + 8;
        int qgA = q0 + qA, qgB = q0 + qB;
        int kt = ktI * 128;
        #pragma unroll
        for (int jj = 0; jj < 2; jj++) {
            int k0c = kt + np*16 + jj*8 + 2*tig;
            e[qA*ESTR + k0c    ] = acc[jj][0] + proj[qA*NB + rpe_clip(qgA - k0c)];
            e[qA*ESTR + k0c + 1] = acc[jj][1] + proj[qA*NB + rpe_clip(qgA - k0c - 1)];
            e[qB*ESTR + k0c    ] = acc[jj][2] + proj[qB*NB + rpe_clip(qgB - k0c)];
            e[qB*ESTR + k0c + 1] = acc[jj][3] + proj[qB*NB + rpe_clip(qgB - k0c - 1)];
        }
        __syncthreads();
    }

    // prefetch V tiles 0,1 (same [t][d] layout as K; overlaps softmax)
    auto fillV = [&](int ktI) {
        uint32_t bU = sKV + (uint32_t)(ktI & 1)*18432;
        const h16* vb = g_vhh + ((size_t)bhid*SEQ + ktI*128)*HDIM;
        #pragma unroll
        for (int it = 0; it < 2; it++) {
            int idx = tid + it*512;
            int r = idx >> 3, c = idx & 7;
            CP16(bU + (uint32_t)(r*144 + c*16), vb + (size_t)r*64 + c*8);
        }
        CP_COMMIT();
    };
    fillV(0);
    fillV(1);

    // ---- softmax + alignment + buckets + P fp16 pack ----
    for (int q = warp*2; q < warp*2 + 2; q++) {
        int qglob = q0 + q;
        float* row = e + q*ESTR;
        float ev[32];
        float mx = -1e30f;
        #pragma unroll
        for (int i = 0; i < 8; i++) {
            float4 vv = *(float4*)&row[i*128 + lane*4];
            ev[i*4+0] = vv.x; ev[i*4+1] = vv.y; ev[i*4+2] = vv.z; ev[i*4+3] = vv.w;
            mx = fmaxf(mx, fmaxf(fmaxf(vv.x, vv.y), fmaxf(vv.z, vv.w)));
        }
        #pragma unroll
        for (int o = 16; o; o >>= 1) mx = fmaxf(mx, __shfl_xor_sync(0xffffffffu, mx, o));
        float sum = 0.f;
        #pragma unroll
        for (int i = 0; i < 32; i++) { ev[i] = __expf(ev[i] - mx); sum += ev[i]; }
        #pragma unroll
        for (int o = 16; o; o >>= 1) sum += __shfl_xor_sync(0xffffffffu, sum, o);
        float inv = 1.f / sum;

        if (lane) srow[q*NB + lane] = 0.f;
        __syncwarp();

        float slo = 0.f, shi = 0.f;
        h16* hid = (h16*)row;
        h16* lod = hid + 1024;
        float* arow = align_out + ((size_t)(bhid * SEQ + qglob)) * SEQ;
        #pragma unroll
        for (int i = 0; i < 8; i++) {
            int k0 = i*128 + lane*4;
            float p[4];
            #pragma unroll
            for (int c = 0; c < 4; c++) p[c] = ev[i*4 + c] * inv;
            *(float4*)&arow[k0] = make_float4(p[0], p[1], p[2], p[3]);
            h16 ph[4];
            #pragma unroll
            for (int c = 0; c < 4; c++) ph[c] = __float2half_rn(p[c]);
            *(uint2*)&hid[k0] = *(uint2*)ph;
            h16 pl[4];
            #pragma unroll
            for (int c = 0; c < 4; c++) pl[c] = __float2half_rn(p[c] - __half2float(ph[c]));
            *(uint2*)&lod[k0] = *(uint2*)pl;
            #pragma unroll
            for (int c = 0; c < 4; c++) {
                int dd = qglob - (k0 + c);
                if (dd >= 16)       slo += p[c];
                else if (dd <= -16) shi += p[c];
                else                srow[q*NB + dd + 16] = p[c];
            }
        }
        #pragma unroll
        for (int o = 16; o; o >>= 1) {
            slo += __shfl_xor_sync(0xffffffffu, slo, o);
            shi += __shfl_xor_sync(0xffffffffu, shi, o);
        }
        if (lane == 0) { srow[q*NB + 32] = slo; srow[q*NB + 0] = shi; }
    }
    __syncthreads();

    // ---- rpecv[32][64] = srow @ rpe_v ----
    for (int i = tid; i < TQ*64; i += 512) {
        int q = i >> 6, d = i & 63;
        float s = 0.f;
        #pragma unroll
        for (int t = 0; t < NB; t++) s += srow[q*NB + t] * rwv[t*64 + d];
        rpecv[i] = s;
    }

    // ---- PV: P (fp16 hi/lo packed in e) x V via trans-LDSM ----
    const int mP = warp & 1;
    const int nt = warp >> 1;
    const uint32_t aoffP = (uint32_t)((lane & 15)*(ESTR*4) + ((lane >> 4) << 4));
    float accP[4] = {0.f, 0.f, 0.f, 0.f};
    for (int ktI = 0; ktI < 8; ktI++) {
        if (ktI < 7) CP_WAIT1(); else CP_WAIT0();
        __syncthreads();
        uint32_t VU = sKV + (uint32_t)(ktI & 1)*18432;
        uint32_t PB = sE + (uint32_t)(mP*16*(ESTR*4)) + aoffP + (uint32_t)(ktI*256);
        #pragma unroll
        for (int ks = 0; ks < 8; ks++) {
            uint32_t ph[4], pl[4], bv[2];
            ldsm4(ph, PB + ks*32);
            ldsm4(pl, PB + 2048 + ks*32);
            ldsm2t(bv, VU + (uint32_t)((ks*16 + (lane & 15))*144 + nt*16));
            mma16h(accP, ph, bv);
            mma16h(accP, pl, bv);
        }
        __syncthreads();
        if (ktI + 2 < 8) fillV(ktI + 2);
    }

    // ---- epilogue: + rpecv, write ctx fp16 hi/lo ----
    {
        int qA = mP*16 + gid, qB = qA + 8;
        int d0 = nt*8 + 2*tig;
        int b = bhid >> 4, h = bhid & 15;
        float v00 = accP[0] + rpecv[qA*64 + d0];
        float v01 = accP[1] + rpecv[qA*64 + d0 + 1];
        float v10 = accP[2] + rpecv[qB*64 + d0];
        float v11 = accP[3] + rpecv[qB*64 + d0 + 1];
        size_t a0 = (size_t)(b*SEQ + q0 + qA)*DIMN + h*HDIM + d0;
        size_t a1 = (size_t)(b*SEQ + q0 + qB)*DIMN + h*HDIM + d0;
        h16 h00 = __float2half_rn(v00), h01 = __float2half_rn(v01);
        h16 h10 = __float2half_rn(v10), h11 = __float2half_rn(v11);
        *(uint32_t*)&g_cxh[a0] = pack2h(v00, v01);
        *(uint32_t*)&g_cxh[a1] = pack2h(v10, v11);
        *(uint32_t*)&g_cxl[a0] = pack2h(v00 - __half2float(h00), v01 - __half2float(h01));
        *(uint32_t*)&g_cxl[a1] = pack2h(v10 - __half2float(h10), v11 - __half2float(h11));
    }
}

// ---------------- launch ---------------------------------------------------
extern "C" void kernel_launch(void* const* d_in, const int* in_sizes, int n_in,
                              void* d_out, int out_size)
{
    const float* q     = (const float*)d_in[0];
    const float* k     = (const float*)d_in[1];
    const float* v     = (const float*)d_in[2];
    const float* Wq    = (const float*)d_in[3];
    const float* bq    = (const float*)d_in[4];
    const float* Wk    = (const float*)d_in[5];
    const float* bk    = (const float*)d_in[6];
    const float* Wv    = (const float*)d_in[7];
    const float* bv    = (const float*)d_in[8];
    const float* rpe_w = (const float*)d_in[9];
    const float* Wo    = (const float*)d_in[10];
    const float* bo    = (const float*)d_in[11];
    float* outp = (float*)d_out;

    static int inited = 0;
    if (!inited) {
        cudaFuncSetAttribute(qkv_gemm_kernel, cudaFuncAttributeMaxDynamicSharedMemorySize, GEMM_SMEM_BYTES);
        cudaFuncSetAttribute(out_gemm_kernel, cudaFuncAttributeMaxDynamicSharedMemorySize, GEMM_SMEM_BYTES);
        cudaFuncSetAttribute(attn_kernel,     cudaFuncAttributeMaxDynamicSharedMemorySize, ATT_SMEM_BYTES);
        inited = 1;
    }

    prep_kernel<<<dim3(GM*GK/4/256, 7), 256>>>(q, k, v, Wq, Wk, Wv, Wo);
    qkv_gemm_kernel<<<dim3(GN/128, GM/128, 3), 256, GEMM_SMEM_BYTES>>>(bq, bk, bv);

    float* align_out = outp + (size_t)BATCH * SEQ * DIMN;
    attn_kernel<<<dim3(SEQ/TQ, BHN), 512, ATT_SMEM_BYTES>>>(rpe_w, align_out);

    out_gemm_kernel<<<dim3(GN/128, GM/128), 256, GEMM_SMEM_BYTES>>>(bo, outp);
}

// round 11
// speedup vs baseline: 1.0836x; 1.0014x over previous
#include <cuda_runtime.h>
#include <cuda_fp16.h>
#include <cstdint>
#include <cstddef>

#define DIMN   1024
#define HEADS  16
#define HDIM   64
#define BATCH  4
#define SEQ    1024
#define BHN    (BATCH*HEADS)
#define NB     33

#define GM (BATCH*SEQ)
#define GN DIMN
#define GK DIMN

typedef __half h16;

// ---------------- scratch (device globals; no allocation allowed) ----------
__device__ h16 g_qxh[GM*GK];          // q input split hi
__device__ h16 g_qxl[GM*GK];          // q input split lo
__device__ h16 g_kxh[GM*GK];          // k input hi only
__device__ h16 g_vxh[GM*GK];          // v input hi only
__device__ h16 g_w[4*(size_t)GN*GK];  // Wq,Wk,Wv,Wo fp16
__device__ h16 g_qhh[BHN*SEQ*HDIM];
__device__ h16 g_qhl[BHN*SEQ*HDIM];
__device__ h16 g_khh[BHN*SEQ*HDIM];
__device__ h16 g_vhh[BHN*SEQ*HDIM];
__device__ h16 g_cxh[GM*DIMN];        // attn ctx hi
__device__ h16 g_cxl[GM*DIMN];        // attn ctx lo

// ---------------- helpers ---------------------------------------------------
__device__ __forceinline__ void mma16h(float* d, const uint32_t* a, const uint32_t* b) {
    asm volatile(
        "mma.sync.aligned.m16n8k16.row.col.f32.f16.f16.f32 "
        "{%0,%1,%2,%3},{%4,%5,%6,%7},{%8,%9},{%0,%1,%2,%3};"
        : "+f"(d[0]), "+f"(d[1]), "+f"(d[2]), "+f"(d[3])
        : "r"(a[0]), "r"(a[1]), "r"(a[2]), "r"(a[3]), "r"(b[0]), "r"(b[1]));
}
__device__ __forceinline__ void ldsm4(uint32_t* r, uint32_t addr) {
    asm volatile("ldmatrix.sync.aligned.m8n8.x4.shared.b16 {%0,%1,%2,%3}, [%4];"
        : "=r"(r[0]), "=r"(r[1]), "=r"(r[2]), "=r"(r[3]) : "r"(addr));
}
__device__ __forceinline__ void ldsm2t(uint32_t* r, uint32_t addr) {
    asm volatile("ldmatrix.sync.aligned.m8n8.x2.trans.shared.b16 {%0,%1}, [%2];"
        : "=r"(r[0]), "=r"(r[1]) : "r"(addr));
}
__device__ __forceinline__ uint32_t smem_u32(const void* p) {
    uint32_t r;
    asm("{ .reg .u64 t; cvta.to.shared.u64 t, %1; cvt.u32.u64 %0, t; }" : "=r"(r) : "l"(p));
    return r;
}
__device__ __forceinline__ uint32_t pack2h(float x, float y) {
    uint32_t r;
    h16 a = __float2half_rn(x), b = __float2half_rn(y);
    asm("mov.b32 %0, {%1, %2};" : "=r"(r) : "h"(*(uint16_t*)&a), "h"(*(uint16_t*)&b));
    return r;
}
#define CP16(dst_u32, src_ptr) \
    asm volatile("cp.async.cg.shared.global [%0], [%1], 16;" :: "r"(dst_u32), "l"(src_ptr))
#define CP_COMMIT() asm volatile("cp.async.commit_group;")
#define CP_WAIT1()  asm volatile("cp.async.wait_group 1;")
#define CP_WAIT0()  asm volatile("cp.async.wait_group 0;")

// ---------------- prep: all splits + conversions in one launch --------------
// job 0: split q -> qxh/qxl; job 1: k -> kxh; job 2: v -> vxh;
// jobs 3-6: Wq,Wk,Wv,Wo -> g_w[job-3]
__global__ __launch_bounds__(256)
void prep_kernel(const float* __restrict__ q, const float* __restrict__ k,
                 const float* __restrict__ v, const float* __restrict__ Wq,
                 const float* __restrict__ Wk, const float* __restrict__ Wv,
                 const float* __restrict__ Wo)
{
    const int job = blockIdx.y;
    const int i = blockIdx.x * 256 + threadIdx.x;
    if (job == 0) {
        if (i >= GM*GK/4) return;
        float4 f4 = ((const float4*)q)[i];
        float f[4] = {f4.x, f4.y, f4.z, f4.w};
        h16 h[4], l[4];
        #pragma unroll
        for (int j = 0; j < 4; j++) {
            h[j] = __float2half_rn(f[j]);
            l[j] = __float2half_rn(f[j] - __half2float(h[j]));
        }
        *(uint2*)&g_qxh[(size_t)i*4] = *(uint2*)h;
        *(uint2*)&g_qxl[(size_t)i*4] = *(uint2*)l;
    } else if (job <= 2) {
        if (i >= GM*GK/4) return;
        const float* s = (job == 1) ? k : v;
        h16* d = (job == 1) ? g_kxh : g_vxh;
        float4 f4 = ((const float4*)s)[i];
        h16 h[4] = { __float2half_rn(f4.x), __float2half_rn(f4.y),
                     __float2half_rn(f4.z), __float2half_rn(f4.w) };
        *(uint2*)&d[(size_t)i*4] = *(uint2*)h;
    } else {
        if (i >= GN*GK/4) return;
        const float* s = (job == 3) ? Wq : (job == 4) ? Wk : (job == 5) ? Wv : Wo;
        h16* d = g_w + (size_t)(job - 3) * GN * GK;
        float4 f4 = ((const float4*)s)[i];
        h16 h[4] = { __float2half_rn(f4.x), __float2half_rn(f4.y),
                     __float2half_rn(f4.z), __float2half_rn(f4.w) };
        *(uint2*)&d[(size_t)i*4] = *(uint2*)h;
    }
}

// ---------------- GEMM core: C = X @ W^T + bias, *scale ---------------------
// 128x128 tile, BK=32, cp.async double-buffered, LDSM fragments.
// mode 0: fp32 out. mode 1: head layout hi+lo. mode 2: head layout hi only.
#define TILEB  (128*80)
#define STAGEB (3*TILEB)
#define GEMM_SMEM_BYTES (2*STAGEB)

__device__ __forceinline__
void gemm_body(const h16* __restrict__ Xh, const h16* __restrict__ Xl,
               const h16* __restrict__ Wh, const float* __restrict__ bias,
               float* __restrict__ outf, h16* __restrict__ oh, h16* __restrict__ ol,
               float scale, int mode, int has_lo, char* gsm)
{
    const uint32_t sb = smem_u32(gsm);
    const int tid  = threadIdx.x;
    const int m0   = blockIdx.y * 128;
    const int n0   = blockIdx.x * 128;
    const int warp = tid >> 5, lane = tid & 31;
    const int gid  = lane >> 2, tig = lane & 3;
    const int wm   = warp >> 2, wn = warp & 3;

    const uint32_t aoffB = (uint32_t)((lane & 15)*80 + ((lane >> 4) << 4));
    const uint32_t boffB = (uint32_t)(((lane & 7) + ((lane >> 4) << 3))*80 + (((lane >> 3) & 1) << 4));

    float acc[4][4][4];
    #pragma unroll
    for (int i = 0; i < 4; i++)
        #pragma unroll
        for (int j = 0; j < 4; j++)
            #pragma unroll
            for (int e = 0; e < 4; e++) acc[i][j][e] = 0.f;

    auto fill = [&](int s) {
        const int k0 = s * 32;
        const uint32_t bU = sb + (uint32_t)(s & 1) * STAGEB;
        #pragma unroll
        for (int it = 0; it < 2; it++) {
            int idx = tid + it * 256;
            int r = idx >> 2, c = idx & 3;
            uint32_t d = (uint32_t)(r*80 + c*16);
            CP16(bU + d,           Xh + (size_t)(m0 + r)*GK + k0 + c*8);
            CP16(bU + 2*TILEB + d, Wh + (size_t)(n0 + r)*GK + k0 + c*8);
            if (has_lo) CP16(bU + TILEB + d, Xl + (size_t)(m0 + r)*GK + k0 + c*8);
        }
        CP_COMMIT();
    };

    fill(0);
    fill(1);
    for (int t = 0; t < 32; t++) {
        if (t < 31) CP_WAIT1(); else CP_WAIT0();
        __syncthreads();

        const uint32_t st  = sb + (uint32_t)(t & 1) * STAGEB;
        #pragma unroll
        for (int kkb = 0; kkb < 64; kkb += 32) {
            uint32_t bf[2][4];
            ldsm4(bf[0], st + 2*TILEB + (uint32_t)((wn*32     )*80) + boffB + kkb);
            ldsm4(bf[1], st + 2*TILEB + (uint32_t)((wn*32 + 16)*80) + boffB + kkb);
            #pragma unroll
            for (int i = 0; i < 4; i++) {
                uint32_t rb = (uint32_t)((wm*64 + i*16)*80) + aoffB + kkb;
                uint32_t ah[4], al[4];
                ldsm4(ah, st + rb);
                if (has_lo) ldsm4(al, st + TILEB + rb);
                #pragma unroll
                for (int j = 0; j < 4; j++) {
                    const uint32_t* b = &bf[j >> 1][(j & 1)*2];
                    mma16h(acc[i][j], ah, b);
                    if (has_lo) mma16h(acc[i][j], al, b);
                }
            }
        }
        __syncthreads();
        if (t + 2 < 32) fill(t + 2);
    }

    #pragma unroll
    for (int i = 0; i < 4; i++) {
        int r0 = m0 + wm*64 + i*16 + gid;
        #pragma unroll
        for (int j = 0; j < 4; j++) {
            int nc = n0 + wn*32 + j*8 + 2*tig;
            float b0 = bias[nc], b1 = bias[nc + 1];
            float v00 = (acc[i][j][0] + b0) * scale;
            float v01 = (acc[i][j][1] + b1) * scale;
            float v10 = (acc[i][j][2] + b0) * scale;
            float v11 = (acc[i][j][3] + b1) * scale;
            if (mode == 0) {
                *(float2*)(outf + (size_t)r0 * GN + nc)       = make_float2(v00, v01);
                *(float2*)(outf + (size_t)(r0 + 8) * GN + nc) = make_float2(v10, v11);
            } else {
                int h = nc >> 6, d = nc & 63;
                int b0i = r0 >> 10, t0 = r0 & (SEQ - 1);
                int b1i = (r0 + 8) >> 10, t1 = (r0 + 8) & (SEQ - 1);
                size_t a0 = ((size_t)((b0i*HEADS + h)*SEQ + t0))*HDIM + d;
                size_t a1 = ((size_t)((b1i*HEADS + h)*SEQ + t1))*HDIM + d;
                *(uint32_t*)&oh[a0] = pack2h(v00, v01);
                *(uint32_t*)&oh[a1] = pack2h(v10, v11);
                if (mode == 1) {
                    h16 h00 = __float2half_rn(v00), h01 = __float2half_rn(v01);
                    h16 h10 = __float2half_rn(v10), h11 = __float2half_rn(v11);
                    *(uint32_t*)&ol[a0] = pack2h(v00 - __half2float(h00), v01 - __half2float(h01));
                    *(uint32_t*)&ol[a1] = pack2h(v10 - __half2float(h10), v11 - __half2float(h11));
                }
            }
        }
    }
}

// batched QKV projections: z=0 Q (hi+lo out, scale 1/8), z=1 K, z=2 V
__global__ __launch_bounds__(256, 2)
void qkv_gemm_kernel(const float* __restrict__ bq, const float* __restrict__ bk,
                     const float* __restrict__ bv)
{
    extern __shared__ char gsm[];
    const int z = blockIdx.z;
    if (z == 0)
        gemm_body(g_qxh, g_qxl, g_w,            bq, nullptr, g_qhh, g_qhl, 0.125f, 1, 1, gsm);
    else if (z == 1)
        gemm_body(g_kxh, nullptr, g_w + (size_t)GN*GK,   bk, nullptr, g_khh, nullptr, 1.0f, 2, 0, gsm);
    else
        gemm_body(g_vxh, nullptr, g_w + 2*(size_t)GN*GK, bv, nullptr, g_vhh, nullptr, 1.0f, 2, 0, gsm);
}

__global__ __launch_bounds__(256, 2)
void out_gemm_kernel(const float* __restrict__ bo, float* __restrict__ outp)
{
    extern __shared__ char gsm[];
    gemm_body(g_cxh, g_cxl, g_w + 3*(size_t)GN*GK, bo, outp, nullptr, nullptr, 1.0f, 0, 1, gsm);
}

// ---------------- attention kernel ------------------------------------------
#define TQ   32
#define ESTR 1036
#define B_E     0
#define B_QH    (TQ*ESTR*4)
#define B_QL    (B_QH + TQ*144)
#define B_KV    (B_QL + TQ*144)
#define B_RWV   (B_KV + 2*18432)
#define B_PROJ  (B_RWV + NB*64*4)
#define B_SROW  (B_PROJ + TQ*NB*4)
#define B_RPECV (B_SROW + TQ*NB*4)
#define ATT_SMEM_BYTES (B_RPECV + TQ*64*4)

__device__ __forceinline__ int rpe_clip(int dd) {
    dd = dd < -16 ? -16 : (dd > 16 ? 16 : dd);
    return dd + 16;
}

__global__ __launch_bounds__(512)
void attn_kernel(const float* __restrict__ rpe_w, float* __restrict__ align_out)
{
    extern __shared__ char smc[];
    float* e     = (float*)smc;
    float* rwv   = (float*)(smc + B_RWV);
    float* proj  = (float*)(smc + B_PROJ);
    float* srow  = (float*)(smc + B_SROW);
    float* rpecv = (float*)(smc + B_RPECV);

    const uint32_t sbase = smem_u32(smc);
    const uint32_t sE = sbase, sQH = sbase + B_QH, sQL = sbase + B_QL, sKV = sbase + B_KV;

    const int bhid = blockIdx.y;
    const int q0   = blockIdx.x * TQ;
    const int tid  = threadIdx.x;
    const int warp = tid >> 5, lane = tid & 31;
    const int gid  = lane >> 2, tig = lane & 3;

    // ---- prologue: Q hi/lo tiles, rpe_v table ----
    {
        int r = (tid & 255) >> 3, c = tid & 7;
        const h16* src = (tid < 256) ? g_qhh : g_qhl;
        char* dst = smc + ((tid < 256) ? B_QH : B_QL);
        *(uint4*)(dst + r*144 + c*16) =
            *(const uint4*)&src[((size_t)bhid*SEQ + q0 + r)*HDIM + c*8];
    }
    for (int i = tid; i < NB*64; i += 512) {
        int t = i >> 6, d = i & 63;
        rwv[i] = rpe_w[t*128 + 64 + d];
    }
    __syncthreads();

    // proj[q][t] = qh[q] . rpe_w[t, 0:64]
    {
        const h16* qh16 = (const h16*)(smc + B_QH);
        const h16* ql16 = (const h16*)(smc + B_QL);
        for (int i = tid; i < TQ*NB; i += 512) {
            int q = i / NB, t = i - q*NB;
            const float* rp = rpe_w + t*128;
            float s = 0.f;
            #pragma unroll 16
            for (int d = 0; d < 64; d++)
                s += (__half2float(qh16[q*72 + d]) + __half2float(ql16[q*72 + d])) * __ldg(&rp[d]);
            proj[i] = s;
        }
    }

    // ---- hoist Q fragments ----
    const int mS = warp & 1;
    const int np = warp >> 1;
    const uint32_t aoffQ = (uint32_t)((lane & 15)*144 + ((lane >> 4) << 4));
    const uint32_t boffS = (uint32_t)(((lane & 7) + ((lane >> 4) << 3))*144 + (((lane >> 3) & 1) << 4));
    uint32_t qhf[4][4], qlf[4][4];
    {
        uint32_t qb = (uint32_t)(mS*16*144) + aoffQ;
        #pragma unroll
        for (int ks = 0; ks < 4; ks++) {
            ldsm4(qhf[ks], sQH + qb + ks*32);
            ldsm4(qlf[ks], sQL + qb + ks*32);
        }
    }

    // ---- S = Q K^T + rpe_q ----
    auto fillK = [&](int ktI) {
        uint32_t bU = sKV + (uint32_t)(ktI & 1)*18432;
        const h16* kb = g_khh + ((size_t)bhid*SEQ + ktI*128)*HDIM;
        #pragma unroll
        for (int it = 0; it < 2; it++) {
            int idx = tid + it*512;
            int r = idx >> 3, c = idx & 7;
            CP16(bU + (uint32_t)(r*144 + c*16), kb + (size_t)r*64 + c*8);
        }
        CP_COMMIT();
    };

    fillK(0);
    for (int ktI = 0; ktI < 8; ktI++) {
        if (ktI < 7) { fillK(ktI + 1); CP_WAIT1(); } else CP_WAIT0();
        __syncthreads();

        uint32_t KU = sKV + (uint32_t)(ktI & 1)*18432 + (uint32_t)(np*16*144);
        float acc[2][4] = {{0.f,0.f,0.f,0.f},{0.f,0.f,0.f,0.f}};
        #pragma unroll
        for (int ks = 0; ks < 4; ks++) {
            uint32_t bf[4];
            ldsm4(bf, KU + boffS + ks*32);
            mma16h(acc[0], qhf[ks], bf);
            mma16h(acc[0], qlf[ks], bf);
            mma16h(acc[1], qhf[ks], bf + 2);
            mma16h(acc[1], qlf[ks], bf + 2);
        }
        int qA = mS*16 + gid, qB = qA + 8;
        int qgA = q0 + qA, qgB = q0 + qB;
        int kt = ktI * 128;
        #pragma unroll
        for (int jj = 0; jj < 2; jj++) {
            int k0c = kt + np*16 + jj*8 + 2*tig;
            e[qA*ESTR + k0c    ] = acc[jj][0] + proj[qA*NB + rpe_clip(qgA - k0c)];
            e[qA*ESTR + k0c + 1] = acc[jj][1] + proj[qA*NB + rpe_clip(qgA - k0c - 1)];
            e[qB*ESTR + k0c    ] = acc[jj][2] + proj[qB*NB + rpe_clip(qgB - k0c)];
            e[qB*ESTR + k0c + 1] = acc[jj][3] + proj[qB*NB + rpe_clip(qgB - k0c - 1)];
        }
        __syncthreads();
    }

    // prefetch V tiles 0,1 (same [t][d] layout as K; overlaps softmax)
    auto fillV = [&](int ktI) {
        uint32_t bU = sKV + (uint32_t)(ktI & 1)*18432;
        const h16* vb = g_vhh + ((size_t)bhid*SEQ + ktI*128)*HDIM;
        #pragma unroll
        for (int it = 0; it < 2; it++) {
            int idx = tid + it*512;
            int r = idx >> 3, c = idx & 7;
            CP16(bU + (uint32_t)(r*144 + c*16), vb + (size_t)r*64 + c*8);
        }
        CP_COMMIT();
    };
    fillV(0);
    fillV(1);

    // ---- softmax + alignment + buckets + P fp16 pack ----
    for (int q = warp*2; q < warp*2 + 2; q++) {
        int qglob = q0 + q;
        float* row = e + q*ESTR;
        float ev[32];
        float mx = -1e30f;
        #pragma unroll
        for (int i = 0; i < 8; i++) {
            float4 vv = *(float4*)&row[i*128 + lane*4];
            ev[i*4+0] = vv.x; ev[i*4+1] = vv.y; ev[i*4+2] = vv.z; ev[i*4+3] = vv.w;
            mx = fmaxf(mx, fmaxf(fmaxf(vv.x, vv.y), fmaxf(vv.z, vv.w)));
        }
        #pragma unroll
        for (int o = 16; o; o >>= 1) mx = fmaxf(mx, __shfl_xor_sync(0xffffffffu, mx, o));
        float sum = 0.f;
        #pragma unroll
        for (int i = 0; i < 32; i++) { ev[i] = __expf(ev[i] - mx); sum += ev[i]; }
        #pragma unroll
        for (int o = 16; o; o >>= 1) sum += __shfl_xor_sync(0xffffffffu, sum, o);
        float inv = 1.f / sum;

        if (lane) srow[q*NB + lane] = 0.f;
        __syncwarp();

        float slo = 0.f, shi = 0.f;
        h16* hid = (h16*)row;
        h16* lod = hid + 1024;
        float* arow = align_out + ((size_t)(bhid * SEQ + qglob)) * SEQ;
        #pragma unroll
        for (int i = 0; i < 8; i++) {
            int k0 = i*128 + lane*4;
            float p[4];
            #pragma unroll
            for (int c = 0; c < 4; c++) p[c] = ev[i*4 + c] * inv;
            *(float4*)&arow[k0] = make_float4(p[0], p[1], p[2], p[3]);
            h16 ph[4];
            #pragma unroll
            for (int c = 0; c < 4; c++) ph[c] = __float2half_rn(p[c]);
            *(uint2*)&hid[k0] = *(uint2*)ph;
            h16 pl[4];
            #pragma unroll
            for (int c = 0; c < 4; c++) pl[c] = __float2half_rn(p[c] - __half2float(ph[c]));
            *(uint2*)&lod[k0] = *(uint2*)pl;
            #pragma unroll
            for (int c = 0; c < 4; c++) {
                int dd = qglob - (k0 + c);
                if (dd >= 16)       slo += p[c];
                else if (dd <= -16) shi += p[c];
                else                srow[q*NB + dd + 16] = p[c];
            }
        }
        #pragma unroll
        for (int o = 16; o; o >>= 1) {
            slo += __shfl_xor_sync(0xffffffffu, slo, o);
            shi += __shfl_xor_sync(0xffffffffu, shi, o);
        }
        if (lane == 0) { srow[q*NB + 32] = slo; srow[q*NB + 0] = shi; }
    }
    __syncthreads();

    // ---- rpecv[32][64] = srow @ rpe_v ----
    for (int i = tid; i < TQ*64; i += 512) {
        int q = i >> 6, d = i & 63;
        float s = 0.f;
        #pragma unroll
        for (int t = 0; t < NB; t++) s += srow[q*NB + t] * rwv[t*64 + d];
        rpecv[i] = s;
    }

    // ---- PV: P (fp16 hi/lo packed in e) x V via trans-LDSM ----
    const int mP = warp & 1;
    const int nt = warp >> 1;
    const uint32_t aoffP = (uint32_t)((lane & 15)*(ESTR*4) + ((lane >> 4) << 4));
    float accP[4] = {0.f, 0.f, 0.f, 0.f};
    for (int ktI = 0; ktI < 8; ktI++) {
        if (ktI < 7) CP_WAIT1(); else CP_WAIT0();
        __syncthreads();
        uint32_t VU = sKV + (uint32_t)(ktI & 1)*18432;
        uint32_t PB = sE + (uint32_t)(mP*16*(ESTR*4)) + aoffP + (uint32_t)(ktI*256);
        #pragma unroll
        for (int ks = 0; ks < 8; ks++) {
            uint32_t ph[4], pl[4], bv[2];
            ldsm4(ph, PB + ks*32);
            ldsm4(pl, PB + 2048 + ks*32);
            ldsm2t(bv, VU + (uint32_t)((ks*16 + (lane & 15))*144 + nt*16));
            mma16h(accP, ph, bv);
            mma16h(accP, pl, bv);
        }
        __syncthreads();
        if (ktI + 2 < 8) fillV(ktI + 2);
    }

    // ---- epilogue: + rpecv, write ctx fp16 hi/lo ----
    {
        int qA = mP*16 + gid, qB = qA + 8;
        int d0 = nt*8 + 2*tig;
        int b = bhid >> 4, h = bhid & 15;
        float v00 = accP[0] + rpecv[qA*64 + d0];
        float v01 = accP[1] + rpecv[qA*64 + d0 + 1];
        float v10 = accP[2] + rpecv[qB*64 + d0];
        float v11 = accP[3] + rpecv[qB*64 + d0 + 1];
        size_t a0 = (size_t)(b*SEQ + q0 + qA)*DIMN + h*HDIM + d0;
        size_t a1 = (size_t)(b*SEQ + q0 + qB)*DIMN + h*HDIM + d0;
        h16 h00 = __float2half_rn(v00), h01 = __float2half_rn(v01);
        h16 h10 = __float2half_rn(v10), h11 = __float2half_rn(v11);
        *(uint32_t*)&g_cxh[a0] = pack2h(v00, v01);
        *(uint32_t*)&g_cxh[a1] = pack2h(v10, v11);
        *(uint32_t*)&g_cxl[a0] = pack2h(v00 - __half2float(h00), v01 - __half2float(h01));
        *(uint32_t*)&g_cxl[a1] = pack2h(v10 - __half2float(h10), v11 - __half2float(h11));
    }
}

// ---------------- launch ---------------------------------------------------
extern "C" void kernel_launch(void* const* d_in, const int* in_sizes, int n_in,
                              void* d_out, int out_size)
{
    const float* q     = (const float*)d_in[0];
    const float* k     = (const float*)d_in[1];
    const float* v     = (const float*)d_in[2];
    const float* Wq    = (const float*)d_in[3];
    const float* bq    = (const float*)d_in[4];
    const float* Wk    = (const float*)d_in[5];
    const float* bk    = (const float*)d_in[6];
    const float* Wv    = (const float*)d_in[7];
    const float* bv    = (const float*)d_in[8];
    const float* rpe_w = (const float*)d_in[9];
    const float* Wo    = (const float*)d_in[10];
    const float* bo    = (const float*)d_in[11];
    float* outp = (float*)d_out;

    static int inited = 0;
    if (!inited) {
        cudaFuncSetAttribute(qkv_gemm_kernel, cudaFuncAttributeMaxDynamicSharedMemorySize, GEMM_SMEM_BYTES);
        cudaFuncSetAttribute(out_gemm_kernel, cudaFuncAttributeMaxDynamicSharedMemorySize, GEMM_SMEM_BYTES);
        cudaFuncSetAttribute(attn_kernel,     cudaFuncAttributeMaxDynamicSharedMemorySize, ATT_SMEM_BYTES);
        inited = 1;
    }

    prep_kernel<<<dim3(GM*GK/4/256, 7), 256>>>(q, k, v, Wq, Wk, Wv, Wo);
    qkv_gemm_kernel<<<dim3(GN/128, GM/128, 3), 256, GEMM_SMEM_BYTES>>>(bq, bk, bv);

    float* align_out = outp + (size_t)BATCH * SEQ * DIMN;
    attn_kernel<<<dim3(SEQ/TQ, BHN), 512, ATT_SMEM_BYTES>>>(rpe_w, align_out);

    out_gemm_kernel<<<dim3(GN/128, GM/128), 256, GEMM_SMEM_BYTES>>>(bo, outp);
}